// round 6
// baseline (speedup 1.0000x reference)
#include <cuda_runtime.h>
#include <math.h>

// Problem constants
#define SS 8192           // spatial length S
#define FF 512            // channels F
#define BB 8              // batch
#define HH 8              // heads
#define DD 64             // head dim
#define MQKV 1536         // 3*F

// ---------------- scratch (device globals; no allocation allowed) ----------------
__device__ float g_scale1[BB*FF], g_shift1[BB*FF];
__device__ float g_scale2[BB*FF], g_shift2[BB*FF];
__device__ float g_kv[BB*HH*DD*DD];          // [b][h][dk][dv]
__device__ float g_ksum[BB*HH*DD];           // [b][h][dk]
__device__ float g_qkv[(size_t)BB*MQKV*SS];  // [b][o][l], o = i*512 + h*64 + d
__device__ float g_attn[(size_t)BB*FF*SS];   // attention out, [b][f][l]
__device__ float g_y[(size_t)BB*FF*SS];      // proj out, [b][F][l]

// ---------------- helpers ----------------
__device__ __forceinline__ float elu1(float x) {
    return x > 0.f ? x + 1.f : expf(x);
}

__device__ __forceinline__ unsigned long long pk2(float x, float y) {
    unsigned long long r;
    asm("mov.b64 %0, {%1,%2};" : "=l"(r) : "f"(x), "f"(y));
    return r;
}
__device__ __forceinline__ float2 upk2(unsigned long long v) {
    float2 r;
    asm("mov.b64 {%0,%1}, %2;" : "=f"(r.x), "=f"(r.y) : "l"(v));
    return r;
}
// packed fp32x2 FMA (sm_100+): d = a*b + c on both lanes
__device__ __forceinline__ unsigned long long ffma2(unsigned long long a,
                                                    unsigned long long b,
                                                    unsigned long long c) {
    unsigned long long d;
    asm("fma.rn.f32x2 %0, %1, %2, %3;" : "=l"(d) : "l"(a), "l"(b), "l"(c));
    return d;
}

// ---------------- GroupNorm stats: per (b, group) mean/rstd -> scale/shift --------
// SRC==0: x = param (hidden_states). SRC==1: x = g_y.
template <int SRC>
__global__ void gn_stats_kernel(const float* __restrict__ xin,
                                const float* __restrict__ gamma,
                                const float* __restrict__ beta) {
    const float* x = (SRC == 0) ? xin : g_y;
    float* scale = (SRC == 0) ? g_scale1 : g_scale2;
    float* shift = (SRC == 0) ? g_shift1 : g_shift2;

    int g = blockIdx.x;           // 0..255
    int b = g >> 5;               // /32
    int grp = g & 31;
    const float4* base = (const float4*)(x + ((size_t)b * FF + (size_t)grp * 16) * SS);

    int tid = threadIdx.x;
    float s = 0.f, ss = 0.f;
    // 16 channels * 8192 = 131072 floats = 32768 float4
    for (int i = tid; i < 32768; i += 256) {
        float4 v = base[i];
        s  += v.x + v.y + v.z + v.w;
        ss += v.x*v.x + v.y*v.y + v.z*v.z + v.w*v.w;
    }
    __shared__ float rs[256], rq[256];
    rs[tid] = s; rq[tid] = ss;
    __syncthreads();
    for (int o = 128; o > 0; o >>= 1) {
        if (tid < o) { rs[tid] += rs[tid + o]; rq[tid] += rq[tid + o]; }
        __syncthreads();
    }
    if (tid < 16) {
        const float inv_n = 1.f / 131072.f;
        float mean = rs[0] * inv_n;
        float var  = rq[0] * inv_n - mean * mean;
        float rstd = rsqrtf(var + 1e-8f);
        int f = grp * 16 + tid;
        float sc = gamma[f] * rstd;
        scale[b * FF + f] = sc;
        shift[b * FF + f] = beta[f] - mean * sc;
    }
}

// ---------------- SGEMM: C[b][m][n] = sum_k A[m][k] * Bop[b][k][n] ---------------
// QKV=true : Bop = affine(hidden) via g_scale1/g_shift1, C = g_qkv (+bias), M=1536
// QKV=false: Bop = g_attn, C = g_y, M=512
// BM=BN=128, BK=16, 256 threads, 8x8 per thread, f32x2 packed accumulators.
template <bool QKV>
__global__ __launch_bounds__(256, 2) void sgemm_kernel(const float* __restrict__ A,
                                                       const float* __restrict__ Bext,
                                                       const float* __restrict__ bias) {
    constexpr int M = QKV ? MQKV : FF;
    const int K = FF, N = SS;

    int b  = blockIdx.z;
    int bm = blockIdx.y * 128;
    int bn = blockIdx.x * 128;

    const float* Bm = QKV ? (Bext + (size_t)b * K * N) : (g_attn + (size_t)b * K * N);
    float* C = QKV ? (g_qkv + (size_t)b * (size_t)M * N) : (g_y + (size_t)b * (size_t)M * N);
    const float* sc = g_scale1 + b * FF;
    const float* sh = g_shift1 + b * FF;

    __shared__ float As[16][132];   // transposed A tile, padded
    __shared__ float Bs[16][128];

    int tid = threadIdx.x;
    int tx = tid & 15, ty = tid >> 4;
    int ar = tid >> 2, ac = (tid & 3) << 2;   // A: row 0..63(+64), col {0,4,8,12}
    int br = tid >> 5, bc = (tid & 31) << 2;  // B: row 0..7(+8),  col 0..124

    unsigned long long c2[8][4];
#pragma unroll
    for (int i = 0; i < 8; i++)
#pragma unroll
        for (int j = 0; j < 4; j++) c2[i][j] = 0ull;

    const float* Ap0 = A + (size_t)(bm + ar) * K + ac;
    const float* Ap1 = A + (size_t)(bm + ar + 64) * K + ac;
    const float* Bp  = Bm + (size_t)br * N + bn + bc;

    for (int k0 = 0; k0 < K; k0 += 16) {
        float4 a0 = *(const float4*)(Ap0 + k0);
        float4 a1 = *(const float4*)(Ap1 + k0);
        float4 b0 = *(const float4*)(Bp + (size_t)k0 * N);
        float4 b1 = *(const float4*)(Bp + (size_t)(k0 + 8) * N);
        if (QKV) {
            float s0 = sc[k0 + br],     t0 = sh[k0 + br];
            float s1 = sc[k0 + br + 8], t1 = sh[k0 + br + 8];
            b0.x = fmaf(b0.x, s0, t0); b0.y = fmaf(b0.y, s0, t0);
            b0.z = fmaf(b0.z, s0, t0); b0.w = fmaf(b0.w, s0, t0);
            b1.x = fmaf(b1.x, s1, t1); b1.y = fmaf(b1.y, s1, t1);
            b1.z = fmaf(b1.z, s1, t1); b1.w = fmaf(b1.w, s1, t1);
        }
        As[ac + 0][ar] = a0.x; As[ac + 1][ar] = a0.y;
        As[ac + 2][ar] = a0.z; As[ac + 3][ar] = a0.w;
        As[ac + 0][ar + 64] = a1.x; As[ac + 1][ar + 64] = a1.y;
        As[ac + 2][ar + 64] = a1.z; As[ac + 3][ar + 64] = a1.w;
        *(float4*)&Bs[br][bc]     = b0;
        *(float4*)&Bs[br + 8][bc] = b1;
        __syncthreads();

#pragma unroll
        for (int kk = 0; kk < 16; kk++) {
            float4 aa0 = *(const float4*)&As[kk][ty * 8];
            float4 aa1 = *(const float4*)&As[kk][ty * 8 + 4];
            const unsigned long long* bp =
                (const unsigned long long*)&Bs[kk][tx * 8];
            unsigned long long bv0 = bp[0], bv1 = bp[1], bv2 = bp[2], bv3 = bp[3];
            float av[8] = {aa0.x, aa0.y, aa0.z, aa0.w, aa1.x, aa1.y, aa1.z, aa1.w};
#pragma unroll
            for (int i = 0; i < 8; i++) {
                unsigned long long ai = pk2(av[i], av[i]);
                c2[i][0] = ffma2(ai, bv0, c2[i][0]);
                c2[i][1] = ffma2(ai, bv1, c2[i][1]);
                c2[i][2] = ffma2(ai, bv2, c2[i][2]);
                c2[i][3] = ffma2(ai, bv3, c2[i][3]);
            }
        }
        __syncthreads();
    }

#pragma unroll
    for (int i = 0; i < 8; i++) {
        int m = bm + ty * 8 + i;
        float bi = QKV ? bias[m] : 0.f;
        float2 p0 = upk2(c2[i][0]), p1 = upk2(c2[i][1]);
        float2 p2 = upk2(c2[i][2]), p3 = upk2(c2[i][3]);
        float4 o0 = {p0.x + bi, p0.y + bi, p1.x + bi, p1.y + bi};
        float4 o1 = {p2.x + bi, p2.y + bi, p3.x + bi, p3.y + bi};
        float* cp = C + (size_t)m * N + bn + tx * 8;
        *(float4*)cp       = o0;
        *(float4*)(cp + 4) = o1;
    }
}

// ---------------- zero kv accumulators ----------------
__global__ void zero_kv_kernel() {
    int i = blockIdx.x * 256 + threadIdx.x;
    if (i < BB*HH*DD*DD) g_kv[i] = 0.f;
    if (i < BB*HH*DD)    g_ksum[i] = 0.f;
}

// ---------------- kv = sum_l k v^T (stored [dk][dv]) and ksum -------------------
__global__ __launch_bounds__(256) void kv_kernel() {
    int chunk = blockIdx.x;  // 0..31, each covers 256 l
    int h = blockIdx.y, b = blockIdx.z;
    const float* kb = g_qkv + ((size_t)b * MQKV + 512  + h * 64) * SS;
    const float* vb = g_qkv + ((size_t)b * MQKV + 1024 + h * 64) * SS;

    __shared__ float ks[64][68];  // [l][d]
    __shared__ float vs[64][68];

    int tid = threadIdx.x;
    int tx = tid & 15, ty = tid >> 4;
    int ld_d = tid >> 2;        // 0..63
    int ld_q = tid & 3;         // 0..3 (l segment of 16)

    float acc[4][4] = {};
    float ksum_acc = 0.f;

    for (int t0 = 0; t0 < 4; t0++) {
        int l0 = chunk * 256 + t0 * 64;
        const float* krow = kb + (size_t)ld_d * SS + l0 + ld_q * 16;
        const float* vrow = vb + (size_t)ld_d * SS + l0 + ld_q * 16;
#pragma unroll
        for (int u = 0; u < 4; u++) {
            float4 kg = *(const float4*)(krow + u * 4);
            float4 vg = *(const float4*)(vrow + u * 4);
            int l = ld_q * 16 + u * 4;
            ks[l + 0][ld_d] = elu1(kg.x); ks[l + 1][ld_d] = elu1(kg.y);
            ks[l + 2][ld_d] = elu1(kg.z); ks[l + 3][ld_d] = elu1(kg.w);
            vs[l + 0][ld_d] = vg.x; vs[l + 1][ld_d] = vg.y;
            vs[l + 2][ld_d] = vg.z; vs[l + 3][ld_d] = vg.w;
        }
        __syncthreads();
#pragma unroll 4
        for (int l = 0; l < 64; l++) {
            float4 kf = *(const float4*)&ks[l][tx * 4];
            float4 vf = *(const float4*)&vs[l][ty * 4];
            acc[0][0] += kf.x * vf.x; acc[0][1] += kf.x * vf.y;
            acc[0][2] += kf.x * vf.z; acc[0][3] += kf.x * vf.w;
            acc[1][0] += kf.y * vf.x; acc[1][1] += kf.y * vf.y;
            acc[1][2] += kf.y * vf.z; acc[1][3] += kf.y * vf.w;
            acc[2][0] += kf.z * vf.x; acc[2][1] += kf.z * vf.y;
            acc[2][2] += kf.z * vf.z; acc[2][3] += kf.z * vf.w;
            acc[3][0] += kf.w * vf.x; acc[3][1] += kf.w * vf.y;
            acc[3][2] += kf.w * vf.z; acc[3][3] += kf.w * vf.w;
        }
        if (tid < 64) {
#pragma unroll 8
            for (int l = 0; l < 64; l++) ksum_acc += ks[l][tid];
        }
        __syncthreads();
    }

    float* kvdst = g_kv + (size_t)(b * 8 + h) * 4096;
#pragma unroll
    for (int i = 0; i < 4; i++)
#pragma unroll
        for (int j = 0; j < 4; j++)
            atomicAdd(&kvdst[(tx * 4 + i) * 64 + (ty * 4 + j)], acc[i][j]);
    if (tid < 64) atomicAdd(&g_ksum[(b * 8 + h) * 64 + tid], ksum_acc);
}

// ---------------- out = (q/z) @ kv -> g_attn[b][f][l] ----------------------------
__global__ __launch_bounds__(256) void attn_out_kernel() {
    int lc = blockIdx.x;            // 0..127, 64 l each
    int h = blockIdx.y, b = blockIdx.z;
    int l0 = lc * 64;
    const float* qb = g_qkv + ((size_t)b * MQKV + h * 64) * SS;

    __shared__ float qs[64][68];    // [d][l]
    __shared__ float kvt[64][64];   // [dk][dv]
    __shared__ float ksum_s[64];
    __shared__ float zs[64];

    int tid = threadIdx.x;
    int tx = tid & 15, ty = tid >> 4;

    const float* kvsrc = g_kv + (size_t)(b * 8 + h) * 4096;
    float* kvflat = &kvt[0][0];
#pragma unroll
    for (int u = 0; u < 4; u++) {
        int idx = u * 1024 + tid * 4;
        *(float4*)(kvflat + idx) = *(const float4*)(kvsrc + idx);
    }
    if (tid < 16)
        *(float4*)&ksum_s[tid * 4] =
            *(const float4*)(g_ksum + (b * 8 + h) * 64 + tid * 4);

    int ld_d = tid >> 2, ld_q = tid & 3;
    const float* qrow = qb + (size_t)ld_d * SS + l0 + ld_q * 16;
#pragma unroll
    for (int u = 0; u < 4; u++) {
        float4 qg = *(const float4*)(qrow + u * 4);
        float4 qe = {elu1(qg.x), elu1(qg.y), elu1(qg.z), elu1(qg.w)};
        *(float4*)&qs[ld_d][ld_q * 16 + u * 4] = qe;
    }
    __syncthreads();

    if (tid < 64) {
        float z = 0.f;
#pragma unroll 8
        for (int d = 0; d < 64; d++) z += qs[d][tid] * ksum_s[d];
        zs[tid] = z;
    }
    __syncthreads();

    float acc[4][4] = {};  // [dv][l]
#pragma unroll 8
    for (int dk = 0; dk < 64; dk++) {
        float4 qf = *(const float4*)&qs[dk][tx * 4];
        float4 kf = *(const float4*)&kvt[dk][ty * 4];
        acc[0][0] += kf.x * qf.x; acc[0][1] += kf.x * qf.y;
        acc[0][2] += kf.x * qf.z; acc[0][3] += kf.x * qf.w;
        acc[1][0] += kf.y * qf.x; acc[1][1] += kf.y * qf.y;
        acc[1][2] += kf.y * qf.z; acc[1][3] += kf.y * qf.w;
        acc[2][0] += kf.z * qf.x; acc[2][1] += kf.z * qf.y;
        acc[2][2] += kf.z * qf.z; acc[2][3] += kf.z * qf.w;
        acc[3][0] += kf.w * qf.x; acc[3][1] += kf.w * qf.y;
        acc[3][2] += kf.w * qf.z; acc[3][3] += kf.w * qf.w;
    }
    float rz0 = 1.f / zs[tx * 4 + 0];
    float rz1 = 1.f / zs[tx * 4 + 1];
    float rz2 = 1.f / zs[tx * 4 + 2];
    float rz3 = 1.f / zs[tx * 4 + 3];

    float* od = g_attn + ((size_t)b * FF + h * 64) * SS + l0;
#pragma unroll
    for (int j = 0; j < 4; j++) {
        float4 o = {acc[j][0] * rz0, acc[j][1] * rz1,
                    acc[j][2] * rz2, acc[j][3] * rz3};
        *(float4*)(od + (size_t)(ty * 4 + j) * SS + tx * 4) = o;
    }
}

// ---------------- final: out = hidden + gate * GN2(y) ---------------------------
__global__ void final_kernel(const float* __restrict__ hs,
                             const float* __restrict__ gate,
                             float* __restrict__ out) {
    size_t i = (size_t)blockIdx.x * 256 + threadIdx.x;  // float4 index
    size_t base = i * 4;
    int row = (int)(base >> 13);  // / 8192
    int f = row & 511;
    int b = row >> 9;
    float sc = g_scale2[b * FF + f];
    float sh = g_shift2[b * FF + f];
    float gt = gate[f];
    float4 hv = *(const float4*)(hs + base);
    float4 yv = *(const float4*)(g_y + base);
    float4 o;
    o.x = hv.x + gt * fmaf(yv.x, sc, sh);
    o.y = hv.y + gt * fmaf(yv.y, sc, sh);
    o.z = hv.z + gt * fmaf(yv.z, sc, sh);
    o.w = hv.w + gt * fmaf(yv.w, sc, sh);
    *(float4*)(out + base) = o;
}

// ---------------- launch ----------------
extern "C" void kernel_launch(void* const* d_in, const int* in_sizes, int n_in,
                              void* d_out, int out_size) {
    const float* hs   = (const float*)d_in[0];  // [B,F,S]
    const float* qkvw = (const float*)d_in[1];  // [3,H,D,F] == [1536][512]
    const float* qkvb = (const float*)d_in[2];  // [1536]
    const float* proj = (const float*)d_in[3];  // [F,F]
    const float* g1g  = (const float*)d_in[4];
    const float* g1b  = (const float*)d_in[5];
    const float* g2g  = (const float*)d_in[6];
    const float* g2b  = (const float*)d_in[7];
    const float* gate = (const float*)d_in[8];  // [F]
    float* out = (float*)d_out;

    gn_stats_kernel<0><<<256, 256>>>(hs, g1g, g1b);
    sgemm_kernel<true><<<dim3(64, 12, 8), 256>>>(qkvw, hs, qkvb);
    zero_kv_kernel<<<1024, 256>>>();
    kv_kernel<<<dim3(32, 8, 8), 256>>>();
    attn_out_kernel<<<dim3(128, 8, 8), 256>>>();
    sgemm_kernel<false><<<dim3(64, 4, 8), 256>>>(proj, nullptr, nullptr);
    gn_stats_kernel<1><<<256, 256>>>(nullptr, g2g, g2b);
    final_kernel<<<32768, 256>>>(hs, gate, out);
}

// round 7
// speedup vs baseline: 1.0008x; 1.0008x over previous
#include <cuda_runtime.h>
#include <math.h>

// Problem constants
#define SS 8192           // spatial length S
#define FF 512            // channels F
#define BB 8              // batch
#define HH 8              // heads
#define DD 64             // head dim
#define MQKV 1536         // 3*F

// ---------------- scratch (device globals; no allocation allowed) ----------------
__device__ float g_scale1[BB*FF], g_shift1[BB*FF];
__device__ float g_scale2[BB*FF], g_shift2[BB*FF];
__device__ float g_kv[BB*HH*DD*DD];          // [b][h][dk][dv]
__device__ float g_ksum[BB*HH*DD];           // [b][h][dk]
__device__ float g_qkv[(size_t)BB*MQKV*SS];  // [b][o][l], o = i*512 + h*64 + d
__device__ float g_attn[(size_t)BB*FF*SS];   // attention out, [b][f][l]
__device__ float g_y[(size_t)BB*FF*SS];      // proj out, [b][F][l]

// ---------------- helpers ----------------
__device__ __forceinline__ float elu1(float x) {
    return x > 0.f ? x + 1.f : expf(x);
}

__device__ __forceinline__ unsigned long long pk2(float x, float y) {
    unsigned long long r;
    asm("mov.b64 %0, {%1,%2};" : "=l"(r) : "f"(x), "f"(y));
    return r;
}
__device__ __forceinline__ float2 upk2(unsigned long long v) {
    float2 r;
    asm("mov.b64 {%0,%1}, %2;" : "=f"(r.x), "=f"(r.y) : "l"(v));
    return r;
}
// packed fp32x2 FMA (sm_100+): d = a*b + c on both lanes
__device__ __forceinline__ unsigned long long ffma2(unsigned long long a,
                                                    unsigned long long b,
                                                    unsigned long long c) {
    unsigned long long d;
    asm("fma.rn.f32x2 %0, %1, %2, %3;" : "=l"(d) : "l"(a), "l"(b), "l"(c));
    return d;
}

// ---------------- GroupNorm stats: per (b, group) mean/rstd -> scale/shift --------
// SRC==0: x = param (hidden_states). SRC==1: x = g_y.
template <int SRC>
__global__ void gn_stats_kernel(const float* __restrict__ xin,
                                const float* __restrict__ gamma,
                                const float* __restrict__ beta) {
    const float* x = (SRC == 0) ? xin : g_y;
    float* scale = (SRC == 0) ? g_scale1 : g_scale2;
    float* shift = (SRC == 0) ? g_shift1 : g_shift2;

    int g = blockIdx.x;           // 0..255
    int b = g >> 5;               // /32
    int grp = g & 31;
    const float4* base = (const float4*)(x + ((size_t)b * FF + (size_t)grp * 16) * SS);

    int tid = threadIdx.x;
    float s = 0.f, ss = 0.f;
    // 16 channels * 8192 = 131072 floats = 32768 float4
    for (int i = tid; i < 32768; i += 256) {
        float4 v = base[i];
        s  += v.x + v.y + v.z + v.w;
        ss += v.x*v.x + v.y*v.y + v.z*v.z + v.w*v.w;
    }
    __shared__ float rs[256], rq[256];
    rs[tid] = s; rq[tid] = ss;
    __syncthreads();
    for (int o = 128; o > 0; o >>= 1) {
        if (tid < o) { rs[tid] += rs[tid + o]; rq[tid] += rq[tid + o]; }
        __syncthreads();
    }
    if (tid < 16) {
        const float inv_n = 1.f / 131072.f;
        float mean = rs[0] * inv_n;
        float var  = rq[0] * inv_n - mean * mean;
        float rstd = rsqrtf(var + 1e-8f);
        int f = grp * 16 + tid;
        float sc = gamma[f] * rstd;
        scale[b * FF + f] = sc;
        shift[b * FF + f] = beta[f] - mean * sc;
    }
}

// ---------------- SGEMM: C[b][m][n] = sum_k A[m][k] * Bop[b][k][n] ---------------
// QKV=true : Bop = affine(hidden) via g_scale1/g_shift1, C = g_qkv (+bias), M=1536
// QKV=false: Bop = g_attn, C = g_y, M=512
// BM=BN=128, BK=16, 256 threads, 8x8 per thread, f32x2 packed accumulators.
template <bool QKV>
__global__ __launch_bounds__(256, 2) void sgemm_kernel(const float* __restrict__ A,
                                                       const float* __restrict__ Bext,
                                                       const float* __restrict__ bias) {
    constexpr int M = QKV ? MQKV : FF;
    const int K = FF, N = SS;

    int b  = blockIdx.z;
    int bm = blockIdx.y * 128;
    int bn = blockIdx.x * 128;

    const float* Bm = QKV ? (Bext + (size_t)b * K * N) : (g_attn + (size_t)b * K * N);
    float* C = QKV ? (g_qkv + (size_t)b * (size_t)M * N) : (g_y + (size_t)b * (size_t)M * N);
    const float* sc = g_scale1 + b * FF;
    const float* sh = g_shift1 + b * FF;

    __shared__ float As[16][132];   // transposed A tile, padded
    __shared__ float Bs[16][128];

    int tid = threadIdx.x;
    int tx = tid & 15, ty = tid >> 4;
    int ar = tid >> 2, ac = (tid & 3) << 2;   // A: row 0..63(+64), col {0,4,8,12}
    int br = tid >> 5, bc = (tid & 31) << 2;  // B: row 0..7(+8),  col 0..124

    unsigned long long c2[8][4];
#pragma unroll
    for (int i = 0; i < 8; i++)
#pragma unroll
        for (int j = 0; j < 4; j++) c2[i][j] = 0ull;

    const float* Ap0 = A + (size_t)(bm + ar) * K + ac;
    const float* Ap1 = A + (size_t)(bm + ar + 64) * K + ac;
    const float* Bp  = Bm + (size_t)br * N + bn + bc;

    for (int k0 = 0; k0 < K; k0 += 16) {
        float4 a0 = *(const float4*)(Ap0 + k0);
        float4 a1 = *(const float4*)(Ap1 + k0);
        float4 b0 = *(const float4*)(Bp + (size_t)k0 * N);
        float4 b1 = *(const float4*)(Bp + (size_t)(k0 + 8) * N);
        if (QKV) {
            float s0 = sc[k0 + br],     t0 = sh[k0 + br];
            float s1 = sc[k0 + br + 8], t1 = sh[k0 + br + 8];
            b0.x = fmaf(b0.x, s0, t0); b0.y = fmaf(b0.y, s0, t0);
            b0.z = fmaf(b0.z, s0, t0); b0.w = fmaf(b0.w, s0, t0);
            b1.x = fmaf(b1.x, s1, t1); b1.y = fmaf(b1.y, s1, t1);
            b1.z = fmaf(b1.z, s1, t1); b1.w = fmaf(b1.w, s1, t1);
        }
        As[ac + 0][ar] = a0.x; As[ac + 1][ar] = a0.y;
        As[ac + 2][ar] = a0.z; As[ac + 3][ar] = a0.w;
        As[ac + 0][ar + 64] = a1.x; As[ac + 1][ar + 64] = a1.y;
        As[ac + 2][ar + 64] = a1.z; As[ac + 3][ar + 64] = a1.w;
        *(float4*)&Bs[br][bc]     = b0;
        *(float4*)&Bs[br + 8][bc] = b1;
        __syncthreads();

#pragma unroll
        for (int kk = 0; kk < 16; kk++) {
            float4 aa0 = *(const float4*)&As[kk][ty * 8];
            float4 aa1 = *(const float4*)&As[kk][ty * 8 + 4];
            const unsigned long long* bp =
                (const unsigned long long*)&Bs[kk][tx * 8];
            unsigned long long bv0 = bp[0], bv1 = bp[1], bv2 = bp[2], bv3 = bp[3];
            float av[8] = {aa0.x, aa0.y, aa0.z, aa0.w, aa1.x, aa1.y, aa1.z, aa1.w};
#pragma unroll
            for (int i = 0; i < 8; i++) {
                unsigned long long ai = pk2(av[i], av[i]);
                c2[i][0] = ffma2(ai, bv0, c2[i][0]);
                c2[i][1] = ffma2(ai, bv1, c2[i][1]);
                c2[i][2] = ffma2(ai, bv2, c2[i][2]);
                c2[i][3] = ffma2(ai, bv3, c2[i][3]);
            }
        }
        __syncthreads();
    }

#pragma unroll
    for (int i = 0; i < 8; i++) {
        int m = bm + ty * 8 + i;
        float bi = QKV ? bias[m] : 0.f;
        float2 p0 = upk2(c2[i][0]), p1 = upk2(c2[i][1]);
        float2 p2 = upk2(c2[i][2]), p3 = upk2(c2[i][3]);
        float4 o0 = {p0.x + bi, p0.y + bi, p1.x + bi, p1.y + bi};
        float4 o1 = {p2.x + bi, p2.y + bi, p3.x + bi, p3.y + bi};
        float* cp = C + (size_t)m * N + bn + tx * 8;
        *(float4*)cp       = o0;
        *(float4*)(cp + 4) = o1;
    }
}

// ---------------- zero kv accumulators ----------------
__global__ void zero_kv_kernel() {
    int i = blockIdx.x * 256 + threadIdx.x;
    if (i < BB*HH*DD*DD) g_kv[i] = 0.f;
    if (i < BB*HH*DD)    g_ksum[i] = 0.f;
}

// ---------------- kv = sum_l k v^T (stored [dk][dv]) and ksum -------------------
__global__ __launch_bounds__(256) void kv_kernel() {
    int chunk = blockIdx.x;  // 0..31, each covers 256 l
    int h = blockIdx.y, b = blockIdx.z;
    const float* kb = g_qkv + ((size_t)b * MQKV + 512  + h * 64) * SS;
    const float* vb = g_qkv + ((size_t)b * MQKV + 1024 + h * 64) * SS;

    __shared__ float ks[64][68];  // [l][d]
    __shared__ float vs[64][68];

    int tid = threadIdx.x;
    int tx = tid & 15, ty = tid >> 4;
    int ld_d = tid >> 2;        // 0..63
    int ld_q = tid & 3;         // 0..3 (l segment of 16)

    float acc[4][4] = {};
    float ksum_acc = 0.f;

    for (int t0 = 0; t0 < 4; t0++) {
        int l0 = chunk * 256 + t0 * 64;
        const float* krow = kb + (size_t)ld_d * SS + l0 + ld_q * 16;
        const float* vrow = vb + (size_t)ld_d * SS + l0 + ld_q * 16;
#pragma unroll
        for (int u = 0; u < 4; u++) {
            float4 kg = *(const float4*)(krow + u * 4);
            float4 vg = *(const float4*)(vrow + u * 4);
            int l = ld_q * 16 + u * 4;
            ks[l + 0][ld_d] = elu1(kg.x); ks[l + 1][ld_d] = elu1(kg.y);
            ks[l + 2][ld_d] = elu1(kg.z); ks[l + 3][ld_d] = elu1(kg.w);
            vs[l + 0][ld_d] = vg.x; vs[l + 1][ld_d] = vg.y;
            vs[l + 2][ld_d] = vg.z; vs[l + 3][ld_d] = vg.w;
        }
        __syncthreads();
#pragma unroll 4
        for (int l = 0; l < 64; l++) {
            float4 kf = *(const float4*)&ks[l][tx * 4];
            float4 vf = *(const float4*)&vs[l][ty * 4];
            acc[0][0] += kf.x * vf.x; acc[0][1] += kf.x * vf.y;
            acc[0][2] += kf.x * vf.z; acc[0][3] += kf.x * vf.w;
            acc[1][0] += kf.y * vf.x; acc[1][1] += kf.y * vf.y;
            acc[1][2] += kf.y * vf.z; acc[1][3] += kf.y * vf.w;
            acc[2][0] += kf.z * vf.x; acc[2][1] += kf.z * vf.y;
            acc[2][2] += kf.z * vf.z; acc[2][3] += kf.z * vf.w;
            acc[3][0] += kf.w * vf.x; acc[3][1] += kf.w * vf.y;
            acc[3][2] += kf.w * vf.z; acc[3][3] += kf.w * vf.w;
        }
        if (tid < 64) {
#pragma unroll 8
            for (int l = 0; l < 64; l++) ksum_acc += ks[l][tid];
        }
        __syncthreads();
    }

    float* kvdst = g_kv + (size_t)(b * 8 + h) * 4096;
#pragma unroll
    for (int i = 0; i < 4; i++)
#pragma unroll
        for (int j = 0; j < 4; j++)
            atomicAdd(&kvdst[(tx * 4 + i) * 64 + (ty * 4 + j)], acc[i][j]);
    if (tid < 64) atomicAdd(&g_ksum[(b * 8 + h) * 64 + tid], ksum_acc);
}

// ---------------- out = (q/z) @ kv -> g_attn[b][f][l] ----------------------------
__global__ __launch_bounds__(256) void attn_out_kernel() {
    int lc = blockIdx.x;            // 0..127, 64 l each
    int h = blockIdx.y, b = blockIdx.z;
    int l0 = lc * 64;
    const float* qb = g_qkv + ((size_t)b * MQKV + h * 64) * SS;

    __shared__ float qs[64][68];    // [d][l]
    __shared__ float kvt[64][64];   // [dk][dv]
    __shared__ float ksum_s[64];
    __shared__ float zs[64];

    int tid = threadIdx.x;
    int tx = tid & 15, ty = tid >> 4;

    const float* kvsrc = g_kv + (size_t)(b * 8 + h) * 4096;
    float* kvflat = &kvt[0][0];
#pragma unroll
    for (int u = 0; u < 4; u++) {
        int idx = u * 1024 + tid * 4;
        *(float4*)(kvflat + idx) = *(const float4*)(kvsrc + idx);
    }
    if (tid < 16)
        *(float4*)&ksum_s[tid * 4] =
            *(const float4*)(g_ksum + (b * 8 + h) * 64 + tid * 4);

    int ld_d = tid >> 2, ld_q = tid & 3;
    const float* qrow = qb + (size_t)ld_d * SS + l0 + ld_q * 16;
#pragma unroll
    for (int u = 0; u < 4; u++) {
        float4 qg = *(const float4*)(qrow + u * 4);
        float4 qe = {elu1(qg.x), elu1(qg.y), elu1(qg.z), elu1(qg.w)};
        *(float4*)&qs[ld_d][ld_q * 16 + u * 4] = qe;
    }
    __syncthreads();

    if (tid < 64) {
        float z = 0.f;
#pragma unroll 8
        for (int d = 0; d < 64; d++) z += qs[d][tid] * ksum_s[d];
        zs[tid] = z;
    }
    __syncthreads();

    float acc[4][4] = {};  // [dv][l]
#pragma unroll 8
    for (int dk = 0; dk < 64; dk++) {
        float4 qf = *(const float4*)&qs[dk][tx * 4];
        float4 kf = *(const float4*)&kvt[dk][ty * 4];
        acc[0][0] += kf.x * qf.x; acc[0][1] += kf.x * qf.y;
        acc[0][2] += kf.x * qf.z; acc[0][3] += kf.x * qf.w;
        acc[1][0] += kf.y * qf.x; acc[1][1] += kf.y * qf.y;
        acc[1][2] += kf.y * qf.z; acc[1][3] += kf.y * qf.w;
        acc[2][0] += kf.z * qf.x; acc[2][1] += kf.z * qf.y;
        acc[2][2] += kf.z * qf.z; acc[2][3] += kf.z * qf.w;
        acc[3][0] += kf.w * qf.x; acc[3][1] += kf.w * qf.y;
        acc[3][2] += kf.w * qf.z; acc[3][3] += kf.w * qf.w;
    }
    float rz0 = 1.f / zs[tx * 4 + 0];
    float rz1 = 1.f / zs[tx * 4 + 1];
    float rz2 = 1.f / zs[tx * 4 + 2];
    float rz3 = 1.f / zs[tx * 4 + 3];

    float* od = g_attn + ((size_t)b * FF + h * 64) * SS + l0;
#pragma unroll
    for (int j = 0; j < 4; j++) {
        float4 o = {acc[j][0] * rz0, acc[j][1] * rz1,
                    acc[j][2] * rz2, acc[j][3] * rz3};
        *(float4*)(od + (size_t)(ty * 4 + j) * SS + tx * 4) = o;
    }
}

// ---------------- final: out = hidden + gate * GN2(y) ---------------------------
__global__ void final_kernel(const float* __restrict__ hs,
                             const float* __restrict__ gate,
                             float* __restrict__ out) {
    size_t i = (size_t)blockIdx.x * 256 + threadIdx.x;  // float4 index
    size_t base = i * 4;
    int row = (int)(base >> 13);  // / 8192
    int f = row & 511;
    int b = row >> 9;
    float sc = g_scale2[b * FF + f];
    float sh = g_shift2[b * FF + f];
    float gt = gate[f];
    float4 hv = *(const float4*)(hs + base);
    float4 yv = *(const float4*)(g_y + base);
    float4 o;
    o.x = hv.x + gt * fmaf(yv.x, sc, sh);
    o.y = hv.y + gt * fmaf(yv.y, sc, sh);
    o.z = hv.z + gt * fmaf(yv.z, sc, sh);
    o.w = hv.w + gt * fmaf(yv.w, sc, sh);
    *(float4*)(out + base) = o;
}

// ---------------- launch ----------------
extern "C" void kernel_launch(void* const* d_in, const int* in_sizes, int n_in,
                              void* d_out, int out_size) {
    const float* hs   = (const float*)d_in[0];  // [B,F,S]
    const float* qkvw = (const float*)d_in[1];  // [3,H,D,F] == [1536][512]
    const float* qkvb = (const float*)d_in[2];  // [1536]
    const float* proj = (const float*)d_in[3];  // [F,F]
    const float* g1g  = (const float*)d_in[4];
    const float* g1b  = (const float*)d_in[5];
    const float* g2g  = (const float*)d_in[6];
    const float* g2b  = (const float*)d_in[7];
    const float* gate = (const float*)d_in[8];  // [F]
    float* out = (float*)d_out;

    gn_stats_kernel<0><<<256, 256>>>(hs, g1g, g1b);
    sgemm_kernel<true><<<dim3(64, 12, 8), 256>>>(qkvw, hs, qkvb);
    zero_kv_kernel<<<1024, 256>>>();
    kv_kernel<<<dim3(32, 8, 8), 256>>>();
    attn_out_kernel<<<dim3(128, 8, 8), 256>>>();
    sgemm_kernel<false><<<dim3(64, 4, 8), 256>>>(proj, nullptr, nullptr);
    gn_stats_kernel<1><<<256, 256>>>(nullptr, g2g, g2b);
    final_kernel<<<32768, 256>>>(hs, gate, out);
}

// round 8
// speedup vs baseline: 1.0013x; 1.0005x over previous
#include <cuda_runtime.h>
#include <math.h>

// Problem constants
#define SS 8192           // spatial length S
#define FF 512            // channels F
#define BB 8              // batch
#define HH 8              // heads
#define DD 64             // head dim
#define MQKV 1536         // 3*F

// ---------------- scratch (device globals; no allocation allowed) ----------------
__device__ float g_scale1[BB*FF], g_shift1[BB*FF];
__device__ float g_scale2[BB*FF], g_shift2[BB*FF];
__device__ float g_kv[BB*HH*DD*DD];          // [b][h][dk][dv]
__device__ float g_ksum[BB*HH*DD];           // [b][h][dk]
__device__ float g_qkv[(size_t)BB*MQKV*SS];  // [b][o][l], o = i*512 + h*64 + d
__device__ float g_attn[(size_t)BB*FF*SS];   // attention out, [b][f][l]
__device__ float g_y[(size_t)BB*FF*SS];      // proj out, [b][F][l]

// ---------------- helpers ----------------
__device__ __forceinline__ float elu1(float x) {
    return x > 0.f ? x + 1.f : expf(x);
}

__device__ __forceinline__ unsigned long long pk2(float x, float y) {
    unsigned long long r;
    asm("mov.b64 %0, {%1,%2};" : "=l"(r) : "f"(x), "f"(y));
    return r;
}
__device__ __forceinline__ float2 upk2(unsigned long long v) {
    float2 r;
    asm("mov.b64 {%0,%1}, %2;" : "=f"(r.x), "=f"(r.y) : "l"(v));
    return r;
}
// packed fp32x2 FMA (sm_100+): d = a*b + c on both lanes
__device__ __forceinline__ unsigned long long ffma2(unsigned long long a,
                                                    unsigned long long b,
                                                    unsigned long long c) {
    unsigned long long d;
    asm("fma.rn.f32x2 %0, %1, %2, %3;" : "=l"(d) : "l"(a), "l"(b), "l"(c));
    return d;
}

// ---------------- GroupNorm stats: per (b, group) mean/rstd -> scale/shift --------
// SRC==0: x = param (hidden_states). SRC==1: x = g_y.
template <int SRC>
__global__ void gn_stats_kernel(const float* __restrict__ xin,
                                const float* __restrict__ gamma,
                                const float* __restrict__ beta) {
    const float* x = (SRC == 0) ? xin : g_y;
    float* scale = (SRC == 0) ? g_scale1 : g_scale2;
    float* shift = (SRC == 0) ? g_shift1 : g_shift2;

    int g = blockIdx.x;           // 0..255
    int b = g >> 5;               // /32
    int grp = g & 31;
    const float4* base = (const float4*)(x + ((size_t)b * FF + (size_t)grp * 16) * SS);

    int tid = threadIdx.x;
    float s = 0.f, ss = 0.f;
    // 16 channels * 8192 = 131072 floats = 32768 float4
    for (int i = tid; i < 32768; i += 256) {
        float4 v = base[i];
        s  += v.x + v.y + v.z + v.w;
        ss += v.x*v.x + v.y*v.y + v.z*v.z + v.w*v.w;
    }
    __shared__ float rs[256], rq[256];
    rs[tid] = s; rq[tid] = ss;
    __syncthreads();
    for (int o = 128; o > 0; o >>= 1) {
        if (tid < o) { rs[tid] += rs[tid + o]; rq[tid] += rq[tid + o]; }
        __syncthreads();
    }
    if (tid < 16) {
        const float inv_n = 1.f / 131072.f;
        float mean = rs[0] * inv_n;
        float var  = rq[0] * inv_n - mean * mean;
        float rstd = rsqrtf(var + 1e-8f);
        int f = grp * 16 + tid;
        float sc = gamma[f] * rstd;
        scale[b * FF + f] = sc;
        shift[b * FF + f] = beta[f] - mean * sc;
    }
}

// ---------------- SGEMM: C[b][m][n] = sum_k A[m][k] * Bop[b][k][n] ---------------
// QKV=true : Bop = affine(hidden) via g_scale1/g_shift1, C = g_qkv (+bias), M=1536
// QKV=false: Bop = g_attn, C = g_y, M=512
// BM=BN=128, BK=16, 256 threads, 8x8 per thread, f32x2 packed accumulators.
template <bool QKV>
__global__ __launch_bounds__(256, 2) void sgemm_kernel(const float* __restrict__ A,
                                                       const float* __restrict__ Bext,
                                                       const float* __restrict__ bias) {
    constexpr int M = QKV ? MQKV : FF;
    const int K = FF, N = SS;

    int b  = blockIdx.z;
    int bm = blockIdx.y * 128;
    int bn = blockIdx.x * 128;

    const float* Bm = QKV ? (Bext + (size_t)b * K * N) : (g_attn + (size_t)b * K * N);
    float* C = QKV ? (g_qkv + (size_t)b * (size_t)M * N) : (g_y + (size_t)b * (size_t)M * N);
    const float* sc = g_scale1 + b * FF;
    const float* sh = g_shift1 + b * FF;

    __shared__ float As[16][132];   // transposed A tile, padded
    __shared__ float Bs[16][128];

    int tid = threadIdx.x;
    int tx = tid & 15, ty = tid >> 4;
    int ar = tid >> 2, ac = (tid & 3) << 2;   // A: row 0..63(+64), col {0,4,8,12}
    int br = tid >> 5, bc = (tid & 31) << 2;  // B: row 0..7(+8),  col 0..124

    unsigned long long c2[8][4];
#pragma unroll
    for (int i = 0; i < 8; i++)
#pragma unroll
        for (int j = 0; j < 4; j++) c2[i][j] = 0ull;

    const float* Ap0 = A + (size_t)(bm + ar) * K + ac;
    const float* Ap1 = A + (size_t)(bm + ar + 64) * K + ac;
    const float* Bp  = Bm + (size_t)br * N + bn + bc;

    for (int k0 = 0; k0 < K; k0 += 16) {
        float4 a0 = *(const float4*)(Ap0 + k0);
        float4 a1 = *(const float4*)(Ap1 + k0);
        float4 b0 = *(const float4*)(Bp + (size_t)k0 * N);
        float4 b1 = *(const float4*)(Bp + (size_t)(k0 + 8) * N);
        if (QKV) {
            float s0 = sc[k0 + br],     t0 = sh[k0 + br];
            float s1 = sc[k0 + br + 8], t1 = sh[k0 + br + 8];
            b0.x = fmaf(b0.x, s0, t0); b0.y = fmaf(b0.y, s0, t0);
            b0.z = fmaf(b0.z, s0, t0); b0.w = fmaf(b0.w, s0, t0);
            b1.x = fmaf(b1.x, s1, t1); b1.y = fmaf(b1.y, s1, t1);
            b1.z = fmaf(b1.z, s1, t1); b1.w = fmaf(b1.w, s1, t1);
        }
        As[ac + 0][ar] = a0.x; As[ac + 1][ar] = a0.y;
        As[ac + 2][ar] = a0.z; As[ac + 3][ar] = a0.w;
        As[ac + 0][ar + 64] = a1.x; As[ac + 1][ar + 64] = a1.y;
        As[ac + 2][ar + 64] = a1.z; As[ac + 3][ar + 64] = a1.w;
        *(float4*)&Bs[br][bc]     = b0;
        *(float4*)&Bs[br + 8][bc] = b1;
        __syncthreads();

#pragma unroll
        for (int kk = 0; kk < 16; kk++) {
            float4 aa0 = *(const float4*)&As[kk][ty * 8];
            float4 aa1 = *(const float4*)&As[kk][ty * 8 + 4];
            const unsigned long long* bp =
                (const unsigned long long*)&Bs[kk][tx * 8];
            unsigned long long bv0 = bp[0], bv1 = bp[1], bv2 = bp[2], bv3 = bp[3];
            float av[8] = {aa0.x, aa0.y, aa0.z, aa0.w, aa1.x, aa1.y, aa1.z, aa1.w};
#pragma unroll
            for (int i = 0; i < 8; i++) {
                unsigned long long ai = pk2(av[i], av[i]);
                c2[i][0] = ffma2(ai, bv0, c2[i][0]);
                c2[i][1] = ffma2(ai, bv1, c2[i][1]);
                c2[i][2] = ffma2(ai, bv2, c2[i][2]);
                c2[i][3] = ffma2(ai, bv3, c2[i][3]);
            }
        }
        __syncthreads();
    }

#pragma unroll
    for (int i = 0; i < 8; i++) {
        int m = bm + ty * 8 + i;
        float bi = QKV ? bias[m] : 0.f;
        float2 p0 = upk2(c2[i][0]), p1 = upk2(c2[i][1]);
        float2 p2 = upk2(c2[i][2]), p3 = upk2(c2[i][3]);
        float4 o0 = {p0.x + bi, p0.y + bi, p1.x + bi, p1.y + bi};
        float4 o1 = {p2.x + bi, p2.y + bi, p3.x + bi, p3.y + bi};
        float* cp = C + (size_t)m * N + bn + tx * 8;
        *(float4*)cp       = o0;
        *(float4*)(cp + 4) = o1;
    }
}

// ---------------- zero kv accumulators ----------------
__global__ void zero_kv_kernel() {
    int i = blockIdx.x * 256 + threadIdx.x;
    if (i < BB*HH*DD*DD) g_kv[i] = 0.f;
    if (i < BB*HH*DD)    g_ksum[i] = 0.f;
}

// ---------------- kv = sum_l k v^T (stored [dk][dv]) and ksum -------------------
__global__ __launch_bounds__(256) void kv_kernel() {
    int chunk = blockIdx.x;  // 0..31, each covers 256 l
    int h = blockIdx.y, b = blockIdx.z;
    const float* kb = g_qkv + ((size_t)b * MQKV + 512  + h * 64) * SS;
    const float* vb = g_qkv + ((size_t)b * MQKV + 1024 + h * 64) * SS;

    __shared__ float ks[64][68];  // [l][d]
    __shared__ float vs[64][68];

    int tid = threadIdx.x;
    int tx = tid & 15, ty = tid >> 4;
    int ld_d = tid >> 2;        // 0..63
    int ld_q = tid & 3;         // 0..3 (l segment of 16)

    float acc[4][4] = {};
    float ksum_acc = 0.f;

    for (int t0 = 0; t0 < 4; t0++) {
        int l0 = chunk * 256 + t0 * 64;
        const float* krow = kb + (size_t)ld_d * SS + l0 + ld_q * 16;
        const float* vrow = vb + (size_t)ld_d * SS + l0 + ld_q * 16;
#pragma unroll
        for (int u = 0; u < 4; u++) {
            float4 kg = *(const float4*)(krow + u * 4);
            float4 vg = *(const float4*)(vrow + u * 4);
            int l = ld_q * 16 + u * 4;
            ks[l + 0][ld_d] = elu1(kg.x); ks[l + 1][ld_d] = elu1(kg.y);
            ks[l + 2][ld_d] = elu1(kg.z); ks[l + 3][ld_d] = elu1(kg.w);
            vs[l + 0][ld_d] = vg.x; vs[l + 1][ld_d] = vg.y;
            vs[l + 2][ld_d] = vg.z; vs[l + 3][ld_d] = vg.w;
        }
        __syncthreads();
#pragma unroll 4
        for (int l = 0; l < 64; l++) {
            float4 kf = *(const float4*)&ks[l][tx * 4];
            float4 vf = *(const float4*)&vs[l][ty * 4];
            acc[0][0] += kf.x * vf.x; acc[0][1] += kf.x * vf.y;
            acc[0][2] += kf.x * vf.z; acc[0][3] += kf.x * vf.w;
            acc[1][0] += kf.y * vf.x; acc[1][1] += kf.y * vf.y;
            acc[1][2] += kf.y * vf.z; acc[1][3] += kf.y * vf.w;
            acc[2][0] += kf.z * vf.x; acc[2][1] += kf.z * vf.y;
            acc[2][2] += kf.z * vf.z; acc[2][3] += kf.z * vf.w;
            acc[3][0] += kf.w * vf.x; acc[3][1] += kf.w * vf.y;
            acc[3][2] += kf.w * vf.z; acc[3][3] += kf.w * vf.w;
        }
        if (tid < 64) {
#pragma unroll 8
            for (int l = 0; l < 64; l++) ksum_acc += ks[l][tid];
        }
        __syncthreads();
    }

    float* kvdst = g_kv + (size_t)(b * 8 + h) * 4096;
#pragma unroll
    for (int i = 0; i < 4; i++)
#pragma unroll
        for (int j = 0; j < 4; j++)
            atomicAdd(&kvdst[(tx * 4 + i) * 64 + (ty * 4 + j)], acc[i][j]);
    if (tid < 64) atomicAdd(&g_ksum[(b * 8 + h) * 64 + tid], ksum_acc);
}

// ---------------- out = (q/z) @ kv -> g_attn[b][f][l] ----------------------------
__global__ __launch_bounds__(256) void attn_out_kernel() {
    int lc = blockIdx.x;            // 0..127, 64 l each
    int h = blockIdx.y, b = blockIdx.z;
    int l0 = lc * 64;
    const float* qb = g_qkv + ((size_t)b * MQKV + h * 64) * SS;

    __shared__ float qs[64][68];    // [d][l]
    __shared__ float kvt[64][64];   // [dk][dv]
    __shared__ float ksum_s[64];
    __shared__ float zs[64];

    int tid = threadIdx.x;
    int tx = tid & 15, ty = tid >> 4;

    const float* kvsrc = g_kv + (size_t)(b * 8 + h) * 4096;
    float* kvflat = &kvt[0][0];
#pragma unroll
    for (int u = 0; u < 4; u++) {
        int idx = u * 1024 + tid * 4;
        *(float4*)(kvflat + idx) = *(const float4*)(kvsrc + idx);
    }
    if (tid < 16)
        *(float4*)&ksum_s[tid * 4] =
            *(const float4*)(g_ksum + (b * 8 + h) * 64 + tid * 4);

    int ld_d = tid >> 2, ld_q = tid & 3;
    const float* qrow = qb + (size_t)ld_d * SS + l0 + ld_q * 16;
#pragma unroll
    for (int u = 0; u < 4; u++) {
        float4 qg = *(const float4*)(qrow + u * 4);
        float4 qe = {elu1(qg.x), elu1(qg.y), elu1(qg.z), elu1(qg.w)};
        *(float4*)&qs[ld_d][ld_q * 16 + u * 4] = qe;
    }
    __syncthreads();

    if (tid < 64) {
        float z = 0.f;
#pragma unroll 8
        for (int d = 0; d < 64; d++) z += qs[d][tid] * ksum_s[d];
        zs[tid] = z;
    }
    __syncthreads();

    float acc[4][4] = {};  // [dv][l]
#pragma unroll 8
    for (int dk = 0; dk < 64; dk++) {
        float4 qf = *(const float4*)&qs[dk][tx * 4];
        float4 kf = *(const float4*)&kvt[dk][ty * 4];
        acc[0][0] += kf.x * qf.x; acc[0][1] += kf.x * qf.y;
        acc[0][2] += kf.x * qf.z; acc[0][3] += kf.x * qf.w;
        acc[1][0] += kf.y * qf.x; acc[1][1] += kf.y * qf.y;
        acc[1][2] += kf.y * qf.z; acc[1][3] += kf.y * qf.w;
        acc[2][0] += kf.z * qf.x; acc[2][1] += kf.z * qf.y;
        acc[2][2] += kf.z * qf.z; acc[2][3] += kf.z * qf.w;
        acc[3][0] += kf.w * qf.x; acc[3][1] += kf.w * qf.y;
        acc[3][2] += kf.w * qf.z; acc[3][3] += kf.w * qf.w;
    }
    float rz0 = 1.f / zs[tx * 4 + 0];
    float rz1 = 1.f / zs[tx * 4 + 1];
    float rz2 = 1.f / zs[tx * 4 + 2];
    float rz3 = 1.f / zs[tx * 4 + 3];

    float* od = g_attn + ((size_t)b * FF + h * 64) * SS + l0;
#pragma unroll
    for (int j = 0; j < 4; j++) {
        float4 o = {acc[j][0] * rz0, acc[j][1] * rz1,
                    acc[j][2] * rz2, acc[j][3] * rz3};
        *(float4*)(od + (size_t)(ty * 4 + j) * SS + tx * 4) = o;
    }
}

// ---------------- final: out = hidden + gate * GN2(y) ---------------------------
__global__ void final_kernel(const float* __restrict__ hs,
                             const float* __restrict__ gate,
                             float* __restrict__ out) {
    size_t i = (size_t)blockIdx.x * 256 + threadIdx.x;  // float4 index
    size_t base = i * 4;
    int row = (int)(base >> 13);  // / 8192
    int f = row & 511;
    int b = row >> 9;
    float sc = g_scale2[b * FF + f];
    float sh = g_shift2[b * FF + f];
    float gt = gate[f];
    float4 hv = *(const float4*)(hs + base);
    float4 yv = *(const float4*)(g_y + base);
    float4 o;
    o.x = hv.x + gt * fmaf(yv.x, sc, sh);
    o.y = hv.y + gt * fmaf(yv.y, sc, sh);
    o.z = hv.z + gt * fmaf(yv.z, sc, sh);
    o.w = hv.w + gt * fmaf(yv.w, sc, sh);
    *(float4*)(out + base) = o;
}

// ---------------- launch ----------------
extern "C" void kernel_launch(void* const* d_in, const int* in_sizes, int n_in,
                              void* d_out, int out_size) {
    const float* hs   = (const float*)d_in[0];  // [B,F,S]
    const float* qkvw = (const float*)d_in[1];  // [3,H,D,F] == [1536][512]
    const float* qkvb = (const float*)d_in[2];  // [1536]
    const float* proj = (const float*)d_in[3];  // [F,F]
    const float* g1g  = (const float*)d_in[4];
    const float* g1b  = (const float*)d_in[5];
    const float* g2g  = (const float*)d_in[6];
    const float* g2b  = (const float*)d_in[7];
    const float* gate = (const float*)d_in[8];  // [F]
    float* out = (float*)d_out;

    gn_stats_kernel<0><<<256, 256>>>(hs, g1g, g1b);
    sgemm_kernel<true><<<dim3(64, 12, 8), 256>>>(qkvw, hs, qkvb);
    zero_kv_kernel<<<1024, 256>>>();
    kv_kernel<<<dim3(32, 8, 8), 256>>>();
    attn_out_kernel<<<dim3(128, 8, 8), 256>>>();
    sgemm_kernel<false><<<dim3(64, 4, 8), 256>>>(proj, nullptr, nullptr);
    gn_stats_kernel<1><<<256, 256>>>(nullptr, g2g, g2b);
    final_kernel<<<32768, 256>>>(hs, gate, out);
}

// round 9
// speedup vs baseline: 1.0019x; 1.0007x over previous
#include <cuda_runtime.h>
#include <math.h>

// Problem constants
#define SS 8192           // spatial length S
#define FF 512            // channels F
#define BB 8              // batch
#define HH 8              // heads
#define DD 64             // head dim
#define MQKV 1536         // 3*F

// ---------------- scratch (device globals; no allocation allowed) ----------------
__device__ float g_scale1[BB*FF], g_shift1[BB*FF];
__device__ float g_scale2[BB*FF], g_shift2[BB*FF];
__device__ float g_kv[BB*HH*DD*DD];          // [b][h][dk][dv]
__device__ float g_ksum[BB*HH*DD];           // [b][h][dk]
__device__ float g_qkv[(size_t)BB*MQKV*SS];  // [b][o][l], o = i*512 + h*64 + d
__device__ float g_attn[(size_t)BB*FF*SS];   // attention out, [b][f][l]
__device__ float g_y[(size_t)BB*FF*SS];      // proj out, [b][F][l]

// ---------------- helpers ----------------
__device__ __forceinline__ float elu1(float x) {
    return x > 0.f ? x + 1.f : expf(x);
}

__device__ __forceinline__ unsigned long long pk2(float x, float y) {
    unsigned long long r;
    asm("mov.b64 %0, {%1,%2};" : "=l"(r) : "f"(x), "f"(y));
    return r;
}
__device__ __forceinline__ float2 upk2(unsigned long long v) {
    float2 r;
    asm("mov.b64 {%0,%1}, %2;" : "=f"(r.x), "=f"(r.y) : "l"(v));
    return r;
}
// packed fp32x2 FMA (sm_100+): d = a*b + c on both lanes
__device__ __forceinline__ unsigned long long ffma2(unsigned long long a,
                                                    unsigned long long b,
                                                    unsigned long long c) {
    unsigned long long d;
    asm("fma.rn.f32x2 %0, %1, %2, %3;" : "=l"(d) : "l"(a), "l"(b), "l"(c));
    return d;
}

// ---------------- GroupNorm stats: per (b, group) mean/rstd -> scale/shift --------
// SRC==0: x = param (hidden_states). SRC==1: x = g_y.
template <int SRC>
__global__ void gn_stats_kernel(const float* __restrict__ xin,
                                const float* __restrict__ gamma,
                                const float* __restrict__ beta) {
    const float* x = (SRC == 0) ? xin : g_y;
    float* scale = (SRC == 0) ? g_scale1 : g_scale2;
    float* shift = (SRC == 0) ? g_shift1 : g_shift2;

    int g = blockIdx.x;           // 0..255
    int b = g >> 5;               // /32
    int grp = g & 31;
    const float4* base = (const float4*)(x + ((size_t)b * FF + (size_t)grp * 16) * SS);

    int tid = threadIdx.x;
    float s = 0.f, ss = 0.f;
    // 16 channels * 8192 = 131072 floats = 32768 float4
    for (int i = tid; i < 32768; i += 256) {
        float4 v = base[i];
        s  += v.x + v.y + v.z + v.w;
        ss += v.x*v.x + v.y*v.y + v.z*v.z + v.w*v.w;
    }
    __shared__ float rs[256], rq[256];
    rs[tid] = s; rq[tid] = ss;
    __syncthreads();
    for (int o = 128; o > 0; o >>= 1) {
        if (tid < o) { rs[tid] += rs[tid + o]; rq[tid] += rq[tid + o]; }
        __syncthreads();
    }
    if (tid < 16) {
        const float inv_n = 1.f / 131072.f;
        float mean = rs[0] * inv_n;
        float var  = rq[0] * inv_n - mean * mean;
        float rstd = rsqrtf(var + 1e-8f);
        int f = grp * 16 + tid;
        float sc = gamma[f] * rstd;
        scale[b * FF + f] = sc;
        shift[b * FF + f] = beta[f] - mean * sc;
    }
}

// ---------------- SGEMM: C[b][m][n] = sum_k A[m][k] * Bop[b][k][n] ---------------
// QKV=true : Bop = affine(hidden) via g_scale1/g_shift1, C = g_qkv (+bias), M=1536
// QKV=false: Bop = g_attn, C = g_y, M=512
// BM=BN=128, BK=16, 256 threads, 8x8 per thread, f32x2 packed accumulators.
template <bool QKV>
__global__ __launch_bounds__(256, 2) void sgemm_kernel(const float* __restrict__ A,
                                                       const float* __restrict__ Bext,
                                                       const float* __restrict__ bias) {
    constexpr int M = QKV ? MQKV : FF;
    const int K = FF, N = SS;

    int b  = blockIdx.z;
    int bm = blockIdx.y * 128;
    int bn = blockIdx.x * 128;

    const float* Bm = QKV ? (Bext + (size_t)b * K * N) : (g_attn + (size_t)b * K * N);
    float* C = QKV ? (g_qkv + (size_t)b * (size_t)M * N) : (g_y + (size_t)b * (size_t)M * N);
    const float* sc = g_scale1 + b * FF;
    const float* sh = g_shift1 + b * FF;

    __shared__ float As[16][132];   // transposed A tile, padded
    __shared__ float Bs[16][128];

    int tid = threadIdx.x;
    int tx = tid & 15, ty = tid >> 4;
    int ar = tid >> 2, ac = (tid & 3) << 2;   // A: row 0..63(+64), col {0,4,8,12}
    int br = tid >> 5, bc = (tid & 31) << 2;  // B: row 0..7(+8),  col 0..124

    unsigned long long c2[8][4];
#pragma unroll
    for (int i = 0; i < 8; i++)
#pragma unroll
        for (int j = 0; j < 4; j++) c2[i][j] = 0ull;

    const float* Ap0 = A + (size_t)(bm + ar) * K + ac;
    const float* Ap1 = A + (size_t)(bm + ar + 64) * K + ac;
    const float* Bp  = Bm + (size_t)br * N + bn + bc;

    for (int k0 = 0; k0 < K; k0 += 16) {
        float4 a0 = *(const float4*)(Ap0 + k0);
        float4 a1 = *(const float4*)(Ap1 + k0);
        float4 b0 = *(const float4*)(Bp + (size_t)k0 * N);
        float4 b1 = *(const float4*)(Bp + (size_t)(k0 + 8) * N);
        if (QKV) {
            float s0 = sc[k0 + br],     t0 = sh[k0 + br];
            float s1 = sc[k0 + br + 8], t1 = sh[k0 + br + 8];
            b0.x = fmaf(b0.x, s0, t0); b0.y = fmaf(b0.y, s0, t0);
            b0.z = fmaf(b0.z, s0, t0); b0.w = fmaf(b0.w, s0, t0);
            b1.x = fmaf(b1.x, s1, t1); b1.y = fmaf(b1.y, s1, t1);
            b1.z = fmaf(b1.z, s1, t1); b1.w = fmaf(b1.w, s1, t1);
        }
        As[ac + 0][ar] = a0.x; As[ac + 1][ar] = a0.y;
        As[ac + 2][ar] = a0.z; As[ac + 3][ar] = a0.w;
        As[ac + 0][ar + 64] = a1.x; As[ac + 1][ar + 64] = a1.y;
        As[ac + 2][ar + 64] = a1.z; As[ac + 3][ar + 64] = a1.w;
        *(float4*)&Bs[br][bc]     = b0;
        *(float4*)&Bs[br + 8][bc] = b1;
        __syncthreads();

#pragma unroll
        for (int kk = 0; kk < 16; kk++) {
            float4 aa0 = *(const float4*)&As[kk][ty * 8];
            float4 aa1 = *(const float4*)&As[kk][ty * 8 + 4];
            const unsigned long long* bp =
                (const unsigned long long*)&Bs[kk][tx * 8];
            unsigned long long bv0 = bp[0], bv1 = bp[1], bv2 = bp[2], bv3 = bp[3];
            float av[8] = {aa0.x, aa0.y, aa0.z, aa0.w, aa1.x, aa1.y, aa1.z, aa1.w};
#pragma unroll
            for (int i = 0; i < 8; i++) {
                unsigned long long ai = pk2(av[i], av[i]);
                c2[i][0] = ffma2(ai, bv0, c2[i][0]);
                c2[i][1] = ffma2(ai, bv1, c2[i][1]);
                c2[i][2] = ffma2(ai, bv2, c2[i][2]);
                c2[i][3] = ffma2(ai, bv3, c2[i][3]);
            }
        }
        __syncthreads();
    }

#pragma unroll
    for (int i = 0; i < 8; i++) {
        int m = bm + ty * 8 + i;
        float bi = QKV ? bias[m] : 0.f;
        float2 p0 = upk2(c2[i][0]), p1 = upk2(c2[i][1]);
        float2 p2 = upk2(c2[i][2]), p3 = upk2(c2[i][3]);
        float4 o0 = {p0.x + bi, p0.y + bi, p1.x + bi, p1.y + bi};
        float4 o1 = {p2.x + bi, p2.y + bi, p3.x + bi, p3.y + bi};
        float* cp = C + (size_t)m * N + bn + tx * 8;
        *(float4*)cp       = o0;
        *(float4*)(cp + 4) = o1;
    }
}

// ---------------- zero kv accumulators ----------------
__global__ void zero_kv_kernel() {
    int i = blockIdx.x * 256 + threadIdx.x;
    if (i < BB*HH*DD*DD) g_kv[i] = 0.f;
    if (i < BB*HH*DD)    g_ksum[i] = 0.f;
}

// ---------------- kv = sum_l k v^T (stored [dk][dv]) and ksum -------------------
__global__ __launch_bounds__(256) void kv_kernel() {
    int chunk = blockIdx.x;  // 0..31, each covers 256 l
    int h = blockIdx.y, b = blockIdx.z;
    const float* kb = g_qkv + ((size_t)b * MQKV + 512  + h * 64) * SS;
    const float* vb = g_qkv + ((size_t)b * MQKV + 1024 + h * 64) * SS;

    __shared__ float ks[64][68];  // [l][d]
    __shared__ float vs[64][68];

    int tid = threadIdx.x;
    int tx = tid & 15, ty = tid >> 4;
    int ld_d = tid >> 2;        // 0..63
    int ld_q = tid & 3;         // 0..3 (l segment of 16)

    float acc[4][4] = {};
    float ksum_acc = 0.f;

    for (int t0 = 0; t0 < 4; t0++) {
        int l0 = chunk * 256 + t0 * 64;
        const float* krow = kb + (size_t)ld_d * SS + l0 + ld_q * 16;
        const float* vrow = vb + (size_t)ld_d * SS + l0 + ld_q * 16;
#pragma unroll
        for (int u = 0; u < 4; u++) {
            float4 kg = *(const float4*)(krow + u * 4);
            float4 vg = *(const float4*)(vrow + u * 4);
            int l = ld_q * 16 + u * 4;
            ks[l + 0][ld_d] = elu1(kg.x); ks[l + 1][ld_d] = elu1(kg.y);
            ks[l + 2][ld_d] = elu1(kg.z); ks[l + 3][ld_d] = elu1(kg.w);
            vs[l + 0][ld_d] = vg.x; vs[l + 1][ld_d] = vg.y;
            vs[l + 2][ld_d] = vg.z; vs[l + 3][ld_d] = vg.w;
        }
        __syncthreads();
#pragma unroll 4
        for (int l = 0; l < 64; l++) {
            float4 kf = *(const float4*)&ks[l][tx * 4];
            float4 vf = *(const float4*)&vs[l][ty * 4];
            acc[0][0] += kf.x * vf.x; acc[0][1] += kf.x * vf.y;
            acc[0][2] += kf.x * vf.z; acc[0][3] += kf.x * vf.w;
            acc[1][0] += kf.y * vf.x; acc[1][1] += kf.y * vf.y;
            acc[1][2] += kf.y * vf.z; acc[1][3] += kf.y * vf.w;
            acc[2][0] += kf.z * vf.x; acc[2][1] += kf.z * vf.y;
            acc[2][2] += kf.z * vf.z; acc[2][3] += kf.z * vf.w;
            acc[3][0] += kf.w * vf.x; acc[3][1] += kf.w * vf.y;
            acc[3][2] += kf.w * vf.z; acc[3][3] += kf.w * vf.w;
        }
        if (tid < 64) {
#pragma unroll 8
            for (int l = 0; l < 64; l++) ksum_acc += ks[l][tid];
        }
        __syncthreads();
    }

    float* kvdst = g_kv + (size_t)(b * 8 + h) * 4096;
#pragma unroll
    for (int i = 0; i < 4; i++)
#pragma unroll
        for (int j = 0; j < 4; j++)
            atomicAdd(&kvdst[(tx * 4 + i) * 64 + (ty * 4 + j)], acc[i][j]);
    if (tid < 64) atomicAdd(&g_ksum[(b * 8 + h) * 64 + tid], ksum_acc);
}

// ---------------- out = (q/z) @ kv -> g_attn[b][f][l] ----------------------------
__global__ __launch_bounds__(256) void attn_out_kernel() {
    int lc = blockIdx.x;            // 0..127, 64 l each
    int h = blockIdx.y, b = blockIdx.z;
    int l0 = lc * 64;
    const float* qb = g_qkv + ((size_t)b * MQKV + h * 64) * SS;

    __shared__ float qs[64][68];    // [d][l]
    __shared__ float kvt[64][64];   // [dk][dv]
    __shared__ float ksum_s[64];
    __shared__ float zs[64];

    int tid = threadIdx.x;
    int tx = tid & 15, ty = tid >> 4;

    const float* kvsrc = g_kv + (size_t)(b * 8 + h) * 4096;
    float* kvflat = &kvt[0][0];
#pragma unroll
    for (int u = 0; u < 4; u++) {
        int idx = u * 1024 + tid * 4;
        *(float4*)(kvflat + idx) = *(const float4*)(kvsrc + idx);
    }
    if (tid < 16)
        *(float4*)&ksum_s[tid * 4] =
            *(const float4*)(g_ksum + (b * 8 + h) * 64 + tid * 4);

    int ld_d = tid >> 2, ld_q = tid & 3;
    const float* qrow = qb + (size_t)ld_d * SS + l0 + ld_q * 16;
#pragma unroll
    for (int u = 0; u < 4; u++) {
        float4 qg = *(const float4*)(qrow + u * 4);
        float4 qe = {elu1(qg.x), elu1(qg.y), elu1(qg.z), elu1(qg.w)};
        *(float4*)&qs[ld_d][ld_q * 16 + u * 4] = qe;
    }
    __syncthreads();

    if (tid < 64) {
        float z = 0.f;
#pragma unroll 8
        for (int d = 0; d < 64; d++) z += qs[d][tid] * ksum_s[d];
        zs[tid] = z;
    }
    __syncthreads();

    float acc[4][4] = {};  // [dv][l]
#pragma unroll 8
    for (int dk = 0; dk < 64; dk++) {
        float4 qf = *(const float4*)&qs[dk][tx * 4];
        float4 kf = *(const float4*)&kvt[dk][ty * 4];
        acc[0][0] += kf.x * qf.x; acc[0][1] += kf.x * qf.y;
        acc[0][2] += kf.x * qf.z; acc[0][3] += kf.x * qf.w;
        acc[1][0] += kf.y * qf.x; acc[1][1] += kf.y * qf.y;
        acc[1][2] += kf.y * qf.z; acc[1][3] += kf.y * qf.w;
        acc[2][0] += kf.z * qf.x; acc[2][1] += kf.z * qf.y;
        acc[2][2] += kf.z * qf.z; acc[2][3] += kf.z * qf.w;
        acc[3][0] += kf.w * qf.x; acc[3][1] += kf.w * qf.y;
        acc[3][2] += kf.w * qf.z; acc[3][3] += kf.w * qf.w;
    }
    float rz0 = 1.f / zs[tx * 4 + 0];
    float rz1 = 1.f / zs[tx * 4 + 1];
    float rz2 = 1.f / zs[tx * 4 + 2];
    float rz3 = 1.f / zs[tx * 4 + 3];

    float* od = g_attn + ((size_t)b * FF + h * 64) * SS + l0;
#pragma unroll
    for (int j = 0; j < 4; j++) {
        float4 o = {acc[j][0] * rz0, acc[j][1] * rz1,
                    acc[j][2] * rz2, acc[j][3] * rz3};
        *(float4*)(od + (size_t)(ty * 4 + j) * SS + tx * 4) = o;
    }
}

// ---------------- final: out = hidden + gate * GN2(y) ---------------------------
__global__ void final_kernel(const float* __restrict__ hs,
                             const float* __restrict__ gate,
                             float* __restrict__ out) {
    size_t i = (size_t)blockIdx.x * 256 + threadIdx.x;  // float4 index
    size_t base = i * 4;
    int row = (int)(base >> 13);  // / 8192
    int f = row & 511;
    int b = row >> 9;
    float sc = g_scale2[b * FF + f];
    float sh = g_shift2[b * FF + f];
    float gt = gate[f];
    float4 hv = *(const float4*)(hs + base);
    float4 yv = *(const float4*)(g_y + base);
    float4 o;
    o.x = hv.x + gt * fmaf(yv.x, sc, sh);
    o.y = hv.y + gt * fmaf(yv.y, sc, sh);
    o.z = hv.z + gt * fmaf(yv.z, sc, sh);
    o.w = hv.w + gt * fmaf(yv.w, sc, sh);
    *(float4*)(out + base) = o;
}

// ---------------- launch ----------------
extern "C" void kernel_launch(void* const* d_in, const int* in_sizes, int n_in,
                              void* d_out, int out_size) {
    const float* hs   = (const float*)d_in[0];  // [B,F,S]
    const float* qkvw = (const float*)d_in[1];  // [3,H,D,F] == [1536][512]
    const float* qkvb = (const float*)d_in[2];  // [1536]
    const float* proj = (const float*)d_in[3];  // [F,F]
    const float* g1g  = (const float*)d_in[4];
    const float* g1b  = (const float*)d_in[5];
    const float* g2g  = (const float*)d_in[6];
    const float* g2b  = (const float*)d_in[7];
    const float* gate = (const float*)d_in[8];  // [F]
    float* out = (float*)d_out;

    gn_stats_kernel<0><<<256, 256>>>(hs, g1g, g1b);
    sgemm_kernel<true><<<dim3(64, 12, 8), 256>>>(qkvw, hs, qkvb);
    zero_kv_kernel<<<1024, 256>>>();
    kv_kernel<<<dim3(32, 8, 8), 256>>>();
    attn_out_kernel<<<dim3(128, 8, 8), 256>>>();
    sgemm_kernel<false><<<dim3(64, 4, 8), 256>>>(proj, nullptr, nullptr);
    gn_stats_kernel<1><<<256, 256>>>(nullptr, g2g, g2b);
    final_kernel<<<32768, 256>>>(hs, gate, out);
}

// round 10
// speedup vs baseline: 1.0021x; 1.0001x over previous
#include <cuda_runtime.h>
#include <math.h>

// Problem constants
#define SS 8192           // spatial length S
#define FF 512            // channels F
#define BB 8              // batch
#define HH 8              // heads
#define DD 64             // head dim
#define MQKV 1536         // 3*F

// ---------------- scratch (device globals; no allocation allowed) ----------------
__device__ float g_scale1[BB*FF], g_shift1[BB*FF];
__device__ float g_scale2[BB*FF], g_shift2[BB*FF];
__device__ float g_kv[BB*HH*DD*DD];          // [b][h][dk][dv]
__device__ float g_ksum[BB*HH*DD];           // [b][h][dk]
__device__ float g_qkv[(size_t)BB*MQKV*SS];  // [b][o][l], o = i*512 + h*64 + d
__device__ float g_attn[(size_t)BB*FF*SS];   // attention out, [b][f][l]
__device__ float g_y[(size_t)BB*FF*SS];      // proj out, [b][F][l]

// ---------------- helpers ----------------
__device__ __forceinline__ float elu1(float x) {
    return x > 0.f ? x + 1.f : expf(x);
}

__device__ __forceinline__ unsigned long long pk2(float x, float y) {
    unsigned long long r;
    asm("mov.b64 %0, {%1,%2};" : "=l"(r) : "f"(x), "f"(y));
    return r;
}
__device__ __forceinline__ float2 upk2(unsigned long long v) {
    float2 r;
    asm("mov.b64 {%0,%1}, %2;" : "=f"(r.x), "=f"(r.y) : "l"(v));
    return r;
}
// packed fp32x2 FMA (sm_100+): d = a*b + c on both lanes
__device__ __forceinline__ unsigned long long ffma2(unsigned long long a,
                                                    unsigned long long b,
                                                    unsigned long long c) {
    unsigned long long d;
    asm("fma.rn.f32x2 %0, %1, %2, %3;" : "=l"(d) : "l"(a), "l"(b), "l"(c));
    return d;
}

// ---------------- GroupNorm stats: per (b, group) mean/rstd -> scale/shift --------
// SRC==0: x = param (hidden_states). SRC==1: x = g_y.
template <int SRC>
__global__ void gn_stats_kernel(const float* __restrict__ xin,
                                const float* __restrict__ gamma,
                                const float* __restrict__ beta) {
    const float* x = (SRC == 0) ? xin : g_y;
    float* scale = (SRC == 0) ? g_scale1 : g_scale2;
    float* shift = (SRC == 0) ? g_shift1 : g_shift2;

    int g = blockIdx.x;           // 0..255
    int b = g >> 5;               // /32
    int grp = g & 31;
    const float4* base = (const float4*)(x + ((size_t)b * FF + (size_t)grp * 16) * SS);

    int tid = threadIdx.x;
    float s = 0.f, ss = 0.f;
    // 16 channels * 8192 = 131072 floats = 32768 float4
    for (int i = tid; i < 32768; i += 256) {
        float4 v = base[i];
        s  += v.x + v.y + v.z + v.w;
        ss += v.x*v.x + v.y*v.y + v.z*v.z + v.w*v.w;
    }
    __shared__ float rs[256], rq[256];
    rs[tid] = s; rq[tid] = ss;
    __syncthreads();
    for (int o = 128; o > 0; o >>= 1) {
        if (tid < o) { rs[tid] += rs[tid + o]; rq[tid] += rq[tid + o]; }
        __syncthreads();
    }
    if (tid < 16) {
        const float inv_n = 1.f / 131072.f;
        float mean = rs[0] * inv_n;
        float var  = rq[0] * inv_n - mean * mean;
        float rstd = rsqrtf(var + 1e-8f);
        int f = grp * 16 + tid;
        float sc = gamma[f] * rstd;
        scale[b * FF + f] = sc;
        shift[b * FF + f] = beta[f] - mean * sc;
    }
}

// ---------------- SGEMM: C[b][m][n] = sum_k A[m][k] * Bop[b][k][n] ---------------
// QKV=true : Bop = affine(hidden) via g_scale1/g_shift1, C = g_qkv (+bias), M=1536
// QKV=false: Bop = g_attn, C = g_y, M=512
// BM=BN=128, BK=16, 256 threads, 8x8 per thread, f32x2 packed accumulators.
template <bool QKV>
__global__ __launch_bounds__(256, 2) void sgemm_kernel(const float* __restrict__ A,
                                                       const float* __restrict__ Bext,
                                                       const float* __restrict__ bias) {
    constexpr int M = QKV ? MQKV : FF;
    const int K = FF, N = SS;

    int b  = blockIdx.z;
    int bm = blockIdx.y * 128;
    int bn = blockIdx.x * 128;

    const float* Bm = QKV ? (Bext + (size_t)b * K * N) : (g_attn + (size_t)b * K * N);
    float* C = QKV ? (g_qkv + (size_t)b * (size_t)M * N) : (g_y + (size_t)b * (size_t)M * N);
    const float* sc = g_scale1 + b * FF;
    const float* sh = g_shift1 + b * FF;

    __shared__ float As[16][132];   // transposed A tile, padded
    __shared__ float Bs[16][128];

    int tid = threadIdx.x;
    int tx = tid & 15, ty = tid >> 4;
    int ar = tid >> 2, ac = (tid & 3) << 2;   // A: row 0..63(+64), col {0,4,8,12}
    int br = tid >> 5, bc = (tid & 31) << 2;  // B: row 0..7(+8),  col 0..124

    unsigned long long c2[8][4];
#pragma unroll
    for (int i = 0; i < 8; i++)
#pragma unroll
        for (int j = 0; j < 4; j++) c2[i][j] = 0ull;

    const float* Ap0 = A + (size_t)(bm + ar) * K + ac;
    const float* Ap1 = A + (size_t)(bm + ar + 64) * K + ac;
    const float* Bp  = Bm + (size_t)br * N + bn + bc;

    for (int k0 = 0; k0 < K; k0 += 16) {
        float4 a0 = *(const float4*)(Ap0 + k0);
        float4 a1 = *(const float4*)(Ap1 + k0);
        float4 b0 = *(const float4*)(Bp + (size_t)k0 * N);
        float4 b1 = *(const float4*)(Bp + (size_t)(k0 + 8) * N);
        if (QKV) {
            float s0 = sc[k0 + br],     t0 = sh[k0 + br];
            float s1 = sc[k0 + br + 8], t1 = sh[k0 + br + 8];
            b0.x = fmaf(b0.x, s0, t0); b0.y = fmaf(b0.y, s0, t0);
            b0.z = fmaf(b0.z, s0, t0); b0.w = fmaf(b0.w, s0, t0);
            b1.x = fmaf(b1.x, s1, t1); b1.y = fmaf(b1.y, s1, t1);
            b1.z = fmaf(b1.z, s1, t1); b1.w = fmaf(b1.w, s1, t1);
        }
        As[ac + 0][ar] = a0.x; As[ac + 1][ar] = a0.y;
        As[ac + 2][ar] = a0.z; As[ac + 3][ar] = a0.w;
        As[ac + 0][ar + 64] = a1.x; As[ac + 1][ar + 64] = a1.y;
        As[ac + 2][ar + 64] = a1.z; As[ac + 3][ar + 64] = a1.w;
        *(float4*)&Bs[br][bc]     = b0;
        *(float4*)&Bs[br + 8][bc] = b1;
        __syncthreads();

#pragma unroll
        for (int kk = 0; kk < 16; kk++) {
            float4 aa0 = *(const float4*)&As[kk][ty * 8];
            float4 aa1 = *(const float4*)&As[kk][ty * 8 + 4];
            const unsigned long long* bp =
                (const unsigned long long*)&Bs[kk][tx * 8];
            unsigned long long bv0 = bp[0], bv1 = bp[1], bv2 = bp[2], bv3 = bp[3];
            float av[8] = {aa0.x, aa0.y, aa0.z, aa0.w, aa1.x, aa1.y, aa1.z, aa1.w};
#pragma unroll
            for (int i = 0; i < 8; i++) {
                unsigned long long ai = pk2(av[i], av[i]);
                c2[i][0] = ffma2(ai, bv0, c2[i][0]);
                c2[i][1] = ffma2(ai, bv1, c2[i][1]);
                c2[i][2] = ffma2(ai, bv2, c2[i][2]);
                c2[i][3] = ffma2(ai, bv3, c2[i][3]);
            }
        }
        __syncthreads();
    }

#pragma unroll
    for (int i = 0; i < 8; i++) {
        int m = bm + ty * 8 + i;
        float bi = QKV ? bias[m] : 0.f;
        float2 p0 = upk2(c2[i][0]), p1 = upk2(c2[i][1]);
        float2 p2 = upk2(c2[i][2]), p3 = upk2(c2[i][3]);
        float4 o0 = {p0.x + bi, p0.y + bi, p1.x + bi, p1.y + bi};
        float4 o1 = {p2.x + bi, p2.y + bi, p3.x + bi, p3.y + bi};
        float* cp = C + (size_t)m * N + bn + tx * 8;
        *(float4*)cp       = o0;
        *(float4*)(cp + 4) = o1;
    }
}

// ---------------- zero kv accumulators ----------------
__global__ void zero_kv_kernel() {
    int i = blockIdx.x * 256 + threadIdx.x;
    if (i < BB*HH*DD*DD) g_kv[i] = 0.f;
    if (i < BB*HH*DD)    g_ksum[i] = 0.f;
}

// ---------------- kv = sum_l k v^T (stored [dk][dv]) and ksum -------------------
__global__ __launch_bounds__(256) void kv_kernel() {
    int chunk = blockIdx.x;  // 0..31, each covers 256 l
    int h = blockIdx.y, b = blockIdx.z;
    const float* kb = g_qkv + ((size_t)b * MQKV + 512  + h * 64) * SS;
    const float* vb = g_qkv + ((size_t)b * MQKV + 1024 + h * 64) * SS;

    __shared__ float ks[64][68];  // [l][d]
    __shared__ float vs[64][68];

    int tid = threadIdx.x;
    int tx = tid & 15, ty = tid >> 4;
    int ld_d = tid >> 2;        // 0..63
    int ld_q = tid & 3;         // 0..3 (l segment of 16)

    float acc[4][4] = {};
    float ksum_acc = 0.f;

    for (int t0 = 0; t0 < 4; t0++) {
        int l0 = chunk * 256 + t0 * 64;
        const float* krow = kb + (size_t)ld_d * SS + l0 + ld_q * 16;
        const float* vrow = vb + (size_t)ld_d * SS + l0 + ld_q * 16;
#pragma unroll
        for (int u = 0; u < 4; u++) {
            float4 kg = *(const float4*)(krow + u * 4);
            float4 vg = *(const float4*)(vrow + u * 4);
            int l = ld_q * 16 + u * 4;
            ks[l + 0][ld_d] = elu1(kg.x); ks[l + 1][ld_d] = elu1(kg.y);
            ks[l + 2][ld_d] = elu1(kg.z); ks[l + 3][ld_d] = elu1(kg.w);
            vs[l + 0][ld_d] = vg.x; vs[l + 1][ld_d] = vg.y;
            vs[l + 2][ld_d] = vg.z; vs[l + 3][ld_d] = vg.w;
        }
        __syncthreads();
#pragma unroll 4
        for (int l = 0; l < 64; l++) {
            float4 kf = *(const float4*)&ks[l][tx * 4];
            float4 vf = *(const float4*)&vs[l][ty * 4];
            acc[0][0] += kf.x * vf.x; acc[0][1] += kf.x * vf.y;
            acc[0][2] += kf.x * vf.z; acc[0][3] += kf.x * vf.w;
            acc[1][0] += kf.y * vf.x; acc[1][1] += kf.y * vf.y;
            acc[1][2] += kf.y * vf.z; acc[1][3] += kf.y * vf.w;
            acc[2][0] += kf.z * vf.x; acc[2][1] += kf.z * vf.y;
            acc[2][2] += kf.z * vf.z; acc[2][3] += kf.z * vf.w;
            acc[3][0] += kf.w * vf.x; acc[3][1] += kf.w * vf.y;
            acc[3][2] += kf.w * vf.z; acc[3][3] += kf.w * vf.w;
        }
        if (tid < 64) {
#pragma unroll 8
            for (int l = 0; l < 64; l++) ksum_acc += ks[l][tid];
        }
        __syncthreads();
    }

    float* kvdst = g_kv + (size_t)(b * 8 + h) * 4096;
#pragma unroll
    for (int i = 0; i < 4; i++)
#pragma unroll
        for (int j = 0; j < 4; j++)
            atomicAdd(&kvdst[(tx * 4 + i) * 64 + (ty * 4 + j)], acc[i][j]);
    if (tid < 64) atomicAdd(&g_ksum[(b * 8 + h) * 64 + tid], ksum_acc);
}

// ---------------- out = (q/z) @ kv -> g_attn[b][f][l] ----------------------------
__global__ __launch_bounds__(256) void attn_out_kernel() {
    int lc = blockIdx.x;            // 0..127, 64 l each
    int h = blockIdx.y, b = blockIdx.z;
    int l0 = lc * 64;
    const float* qb = g_qkv + ((size_t)b * MQKV + h * 64) * SS;

    __shared__ float qs[64][68];    // [d][l]
    __shared__ float kvt[64][64];   // [dk][dv]
    __shared__ float ksum_s[64];
    __shared__ float zs[64];

    int tid = threadIdx.x;
    int tx = tid & 15, ty = tid >> 4;

    const float* kvsrc = g_kv + (size_t)(b * 8 + h) * 4096;
    float* kvflat = &kvt[0][0];
#pragma unroll
    for (int u = 0; u < 4; u++) {
        int idx = u * 1024 + tid * 4;
        *(float4*)(kvflat + idx) = *(const float4*)(kvsrc + idx);
    }
    if (tid < 16)
        *(float4*)&ksum_s[tid * 4] =
            *(const float4*)(g_ksum + (b * 8 + h) * 64 + tid * 4);

    int ld_d = tid >> 2, ld_q = tid & 3;
    const float* qrow = qb + (size_t)ld_d * SS + l0 + ld_q * 16;
#pragma unroll
    for (int u = 0; u < 4; u++) {
        float4 qg = *(const float4*)(qrow + u * 4);
        float4 qe = {elu1(qg.x), elu1(qg.y), elu1(qg.z), elu1(qg.w)};
        *(float4*)&qs[ld_d][ld_q * 16 + u * 4] = qe;
    }
    __syncthreads();

    if (tid < 64) {
        float z = 0.f;
#pragma unroll 8
        for (int d = 0; d < 64; d++) z += qs[d][tid] * ksum_s[d];
        zs[tid] = z;
    }
    __syncthreads();

    float acc[4][4] = {};  // [dv][l]
#pragma unroll 8
    for (int dk = 0; dk < 64; dk++) {
        float4 qf = *(const float4*)&qs[dk][tx * 4];
        float4 kf = *(const float4*)&kvt[dk][ty * 4];
        acc[0][0] += kf.x * qf.x; acc[0][1] += kf.x * qf.y;
        acc[0][2] += kf.x * qf.z; acc[0][3] += kf.x * qf.w;
        acc[1][0] += kf.y * qf.x; acc[1][1] += kf.y * qf.y;
        acc[1][2] += kf.y * qf.z; acc[1][3] += kf.y * qf.w;
        acc[2][0] += kf.z * qf.x; acc[2][1] += kf.z * qf.y;
        acc[2][2] += kf.z * qf.z; acc[2][3] += kf.z * qf.w;
        acc[3][0] += kf.w * qf.x; acc[3][1] += kf.w * qf.y;
        acc[3][2] += kf.w * qf.z; acc[3][3] += kf.w * qf.w;
    }
    float rz0 = 1.f / zs[tx * 4 + 0];
    float rz1 = 1.f / zs[tx * 4 + 1];
    float rz2 = 1.f / zs[tx * 4 + 2];
    float rz3 = 1.f / zs[tx * 4 + 3];

    float* od = g_attn + ((size_t)b * FF + h * 64) * SS + l0;
#pragma unroll
    for (int j = 0; j < 4; j++) {
        float4 o = {acc[j][0] * rz0, acc[j][1] * rz1,
                    acc[j][2] * rz2, acc[j][3] * rz3};
        *(float4*)(od + (size_t)(ty * 4 + j) * SS + tx * 4) = o;
    }
}

// ---------------- final: out = hidden + gate * GN2(y) ---------------------------
__global__ void final_kernel(const float* __restrict__ hs,
                             const float* __restrict__ gate,
                             float* __restrict__ out) {
    size_t i = (size_t)blockIdx.x * 256 + threadIdx.x;  // float4 index
    size_t base = i * 4;
    int row = (int)(base >> 13);  // / 8192
    int f = row & 511;
    int b = row >> 9;
    float sc = g_scale2[b * FF + f];
    float sh = g_shift2[b * FF + f];
    float gt = gate[f];
    float4 hv = *(const float4*)(hs + base);
    float4 yv = *(const float4*)(g_y + base);
    float4 o;
    o.x = hv.x + gt * fmaf(yv.x, sc, sh);
    o.y = hv.y + gt * fmaf(yv.y, sc, sh);
    o.z = hv.z + gt * fmaf(yv.z, sc, sh);
    o.w = hv.w + gt * fmaf(yv.w, sc, sh);
    *(float4*)(out + base) = o;
}

// ---------------- launch ----------------
extern "C" void kernel_launch(void* const* d_in, const int* in_sizes, int n_in,
                              void* d_out, int out_size) {
    const float* hs   = (const float*)d_in[0];  // [B,F,S]
    const float* qkvw = (const float*)d_in[1];  // [3,H,D,F] == [1536][512]
    const float* qkvb = (const float*)d_in[2];  // [1536]
    const float* proj = (const float*)d_in[3];  // [F,F]
    const float* g1g  = (const float*)d_in[4];
    const float* g1b  = (const float*)d_in[5];
    const float* g2g  = (const float*)d_in[6];
    const float* g2b  = (const float*)d_in[7];
    const float* gate = (const float*)d_in[8];  // [F]
    float* out = (float*)d_out;

    gn_stats_kernel<0><<<256, 256>>>(hs, g1g, g1b);
    sgemm_kernel<true><<<dim3(64, 12, 8), 256>>>(qkvw, hs, qkvb);
    zero_kv_kernel<<<1024, 256>>>();
    kv_kernel<<<dim3(32, 8, 8), 256>>>();
    attn_out_kernel<<<dim3(128, 8, 8), 256>>>();
    sgemm_kernel<false><<<dim3(64, 4, 8), 256>>>(proj, nullptr, nullptr);
    gn_stats_kernel<1><<<256, 256>>>(nullptr, g2g, g2b);
    final_kernel<<<32768, 256>>>(hs, gate, out);
}

// round 11
// speedup vs baseline: 1.0025x; 1.0005x over previous
#include <cuda_runtime.h>
#include <math.h>

// Problem constants
#define SS 8192           // spatial length S
#define FF 512            // channels F
#define BB 8              // batch
#define HH 8              // heads
#define DD 64             // head dim
#define MQKV 1536         // 3*F

// ---------------- scratch (device globals; no allocation allowed) ----------------
__device__ float g_scale1[BB*FF], g_shift1[BB*FF];
__device__ float g_scale2[BB*FF], g_shift2[BB*FF];
__device__ float g_kv[BB*HH*DD*DD];          // [b][h][dk][dv]
__device__ float g_ksum[BB*HH*DD];           // [b][h][dk]
__device__ float g_qkv[(size_t)BB*MQKV*SS];  // [b][o][l], o = i*512 + h*64 + d
__device__ float g_attn[(size_t)BB*FF*SS];   // attention out, [b][f][l]
__device__ float g_y[(size_t)BB*FF*SS];      // proj out, [b][F][l]

// ---------------- helpers ----------------
__device__ __forceinline__ float elu1(float x) {
    return x > 0.f ? x + 1.f : expf(x);
}

__device__ __forceinline__ unsigned long long pk2(float x, float y) {
    unsigned long long r;
    asm("mov.b64 %0, {%1,%2};" : "=l"(r) : "f"(x), "f"(y));
    return r;
}
__device__ __forceinline__ float2 upk2(unsigned long long v) {
    float2 r;
    asm("mov.b64 {%0,%1}, %2;" : "=f"(r.x), "=f"(r.y) : "l"(v));
    return r;
}
// packed fp32x2 FMA (sm_100+): d = a*b + c on both lanes
__device__ __forceinline__ unsigned long long ffma2(unsigned long long a,
                                                    unsigned long long b,
                                                    unsigned long long c) {
    unsigned long long d;
    asm("fma.rn.f32x2 %0, %1, %2, %3;" : "=l"(d) : "l"(a), "l"(b), "l"(c));
    return d;
}

// ---------------- GroupNorm stats: per (b, group) mean/rstd -> scale/shift --------
// SRC==0: x = param (hidden_states). SRC==1: x = g_y.
template <int SRC>
__global__ void gn_stats_kernel(const float* __restrict__ xin,
                                const float* __restrict__ gamma,
                                const float* __restrict__ beta) {
    const float* x = (SRC == 0) ? xin : g_y;
    float* scale = (SRC == 0) ? g_scale1 : g_scale2;
    float* shift = (SRC == 0) ? g_shift1 : g_shift2;

    int g = blockIdx.x;           // 0..255
    int b = g >> 5;               // /32
    int grp = g & 31;
    const float4* base = (const float4*)(x + ((size_t)b * FF + (size_t)grp * 16) * SS);

    int tid = threadIdx.x;
    float s = 0.f, ss = 0.f;
    // 16 channels * 8192 = 131072 floats = 32768 float4
    for (int i = tid; i < 32768; i += 256) {
        float4 v = base[i];
        s  += v.x + v.y + v.z + v.w;
        ss += v.x*v.x + v.y*v.y + v.z*v.z + v.w*v.w;
    }
    __shared__ float rs[256], rq[256];
    rs[tid] = s; rq[tid] = ss;
    __syncthreads();
    for (int o = 128; o > 0; o >>= 1) {
        if (tid < o) { rs[tid] += rs[tid + o]; rq[tid] += rq[tid + o]; }
        __syncthreads();
    }
    if (tid < 16) {
        const float inv_n = 1.f / 131072.f;
        float mean = rs[0] * inv_n;
        float var  = rq[0] * inv_n - mean * mean;
        float rstd = rsqrtf(var + 1e-8f);
        int f = grp * 16 + tid;
        float sc = gamma[f] * rstd;
        scale[b * FF + f] = sc;
        shift[b * FF + f] = beta[f] - mean * sc;
    }
}

// ---------------- SGEMM: C[b][m][n] = sum_k A[m][k] * Bop[b][k][n] ---------------
// QKV=true : Bop = affine(hidden) via g_scale1/g_shift1, C = g_qkv (+bias), M=1536
// QKV=false: Bop = g_attn, C = g_y, M=512
// BM=BN=128, BK=16, 256 threads, 8x8 per thread, f32x2 packed accumulators.
template <bool QKV>
__global__ __launch_bounds__(256, 2) void sgemm_kernel(const float* __restrict__ A,
                                                       const float* __restrict__ Bext,
                                                       const float* __restrict__ bias) {
    constexpr int M = QKV ? MQKV : FF;
    const int K = FF, N = SS;

    int b  = blockIdx.z;
    int bm = blockIdx.y * 128;
    int bn = blockIdx.x * 128;

    const float* Bm = QKV ? (Bext + (size_t)b * K * N) : (g_attn + (size_t)b * K * N);
    float* C = QKV ? (g_qkv + (size_t)b * (size_t)M * N) : (g_y + (size_t)b * (size_t)M * N);
    const float* sc = g_scale1 + b * FF;
    const float* sh = g_shift1 + b * FF;

    __shared__ float As[16][132];   // transposed A tile, padded
    __shared__ float Bs[16][128];

    int tid = threadIdx.x;
    int tx = tid & 15, ty = tid >> 4;
    int ar = tid >> 2, ac = (tid & 3) << 2;   // A: row 0..63(+64), col {0,4,8,12}
    int br = tid >> 5, bc = (tid & 31) << 2;  // B: row 0..7(+8),  col 0..124

    unsigned long long c2[8][4];
#pragma unroll
    for (int i = 0; i < 8; i++)
#pragma unroll
        for (int j = 0; j < 4; j++) c2[i][j] = 0ull;

    const float* Ap0 = A + (size_t)(bm + ar) * K + ac;
    const float* Ap1 = A + (size_t)(bm + ar + 64) * K + ac;
    const float* Bp  = Bm + (size_t)br * N + bn + bc;

    for (int k0 = 0; k0 < K; k0 += 16) {
        float4 a0 = *(const float4*)(Ap0 + k0);
        float4 a1 = *(const float4*)(Ap1 + k0);
        float4 b0 = *(const float4*)(Bp + (size_t)k0 * N);
        float4 b1 = *(const float4*)(Bp + (size_t)(k0 + 8) * N);
        if (QKV) {
            float s0 = sc[k0 + br],     t0 = sh[k0 + br];
            float s1 = sc[k0 + br + 8], t1 = sh[k0 + br + 8];
            b0.x = fmaf(b0.x, s0, t0); b0.y = fmaf(b0.y, s0, t0);
            b0.z = fmaf(b0.z, s0, t0); b0.w = fmaf(b0.w, s0, t0);
            b1.x = fmaf(b1.x, s1, t1); b1.y = fmaf(b1.y, s1, t1);
            b1.z = fmaf(b1.z, s1, t1); b1.w = fmaf(b1.w, s1, t1);
        }
        As[ac + 0][ar] = a0.x; As[ac + 1][ar] = a0.y;
        As[ac + 2][ar] = a0.z; As[ac + 3][ar] = a0.w;
        As[ac + 0][ar + 64] = a1.x; As[ac + 1][ar + 64] = a1.y;
        As[ac + 2][ar + 64] = a1.z; As[ac + 3][ar + 64] = a1.w;
        *(float4*)&Bs[br][bc]     = b0;
        *(float4*)&Bs[br + 8][bc] = b1;
        __syncthreads();

#pragma unroll
        for (int kk = 0; kk < 16; kk++) {
            float4 aa0 = *(const float4*)&As[kk][ty * 8];
            float4 aa1 = *(const float4*)&As[kk][ty * 8 + 4];
            const unsigned long long* bp =
                (const unsigned long long*)&Bs[kk][tx * 8];
            unsigned long long bv0 = bp[0], bv1 = bp[1], bv2 = bp[2], bv3 = bp[3];
            float av[8] = {aa0.x, aa0.y, aa0.z, aa0.w, aa1.x, aa1.y, aa1.z, aa1.w};
#pragma unroll
            for (int i = 0; i < 8; i++) {
                unsigned long long ai = pk2(av[i], av[i]);
                c2[i][0] = ffma2(ai, bv0, c2[i][0]);
                c2[i][1] = ffma2(ai, bv1, c2[i][1]);
                c2[i][2] = ffma2(ai, bv2, c2[i][2]);
                c2[i][3] = ffma2(ai, bv3, c2[i][3]);
            }
        }
        __syncthreads();
    }

#pragma unroll
    for (int i = 0; i < 8; i++) {
        int m = bm + ty * 8 + i;
        float bi = QKV ? bias[m] : 0.f;
        float2 p0 = upk2(c2[i][0]), p1 = upk2(c2[i][1]);
        float2 p2 = upk2(c2[i][2]), p3 = upk2(c2[i][3]);
        float4 o0 = {p0.x + bi, p0.y + bi, p1.x + bi, p1.y + bi};
        float4 o1 = {p2.x + bi, p2.y + bi, p3.x + bi, p3.y + bi};
        float* cp = C + (size_t)m * N + bn + tx * 8;
        *(float4*)cp       = o0;
        *(float4*)(cp + 4) = o1;
    }
}

// ---------------- zero kv accumulators ----------------
__global__ void zero_kv_kernel() {
    int i = blockIdx.x * 256 + threadIdx.x;
    if (i < BB*HH*DD*DD) g_kv[i] = 0.f;
    if (i < BB*HH*DD)    g_ksum[i] = 0.f;
}

// ---------------- kv = sum_l k v^T (stored [dk][dv]) and ksum -------------------
__global__ __launch_bounds__(256) void kv_kernel() {
    int chunk = blockIdx.x;  // 0..31, each covers 256 l
    int h = blockIdx.y, b = blockIdx.z;
    const float* kb = g_qkv + ((size_t)b * MQKV + 512  + h * 64) * SS;
    const float* vb = g_qkv + ((size_t)b * MQKV + 1024 + h * 64) * SS;

    __shared__ float ks[64][68];  // [l][d]
    __shared__ float vs[64][68];

    int tid = threadIdx.x;
    int tx = tid & 15, ty = tid >> 4;
    int ld_d = tid >> 2;        // 0..63
    int ld_q = tid & 3;         // 0..3 (l segment of 16)

    float acc[4][4] = {};
    float ksum_acc = 0.f;

    for (int t0 = 0; t0 < 4; t0++) {
        int l0 = chunk * 256 + t0 * 64;
        const float* krow = kb + (size_t)ld_d * SS + l0 + ld_q * 16;
        const float* vrow = vb + (size_t)ld_d * SS + l0 + ld_q * 16;
#pragma unroll
        for (int u = 0; u < 4; u++) {
            float4 kg = *(const float4*)(krow + u * 4);
            float4 vg = *(const float4*)(vrow + u * 4);
            int l = ld_q * 16 + u * 4;
            ks[l + 0][ld_d] = elu1(kg.x); ks[l + 1][ld_d] = elu1(kg.y);
            ks[l + 2][ld_d] = elu1(kg.z); ks[l + 3][ld_d] = elu1(kg.w);
            vs[l + 0][ld_d] = vg.x; vs[l + 1][ld_d] = vg.y;
            vs[l + 2][ld_d] = vg.z; vs[l + 3][ld_d] = vg.w;
        }
        __syncthreads();
#pragma unroll 4
        for (int l = 0; l < 64; l++) {
            float4 kf = *(const float4*)&ks[l][tx * 4];
            float4 vf = *(const float4*)&vs[l][ty * 4];
            acc[0][0] += kf.x * vf.x; acc[0][1] += kf.x * vf.y;
            acc[0][2] += kf.x * vf.z; acc[0][3] += kf.x * vf.w;
            acc[1][0] += kf.y * vf.x; acc[1][1] += kf.y * vf.y;
            acc[1][2] += kf.y * vf.z; acc[1][3] += kf.y * vf.w;
            acc[2][0] += kf.z * vf.x; acc[2][1] += kf.z * vf.y;
            acc[2][2] += kf.z * vf.z; acc[2][3] += kf.z * vf.w;
            acc[3][0] += kf.w * vf.x; acc[3][1] += kf.w * vf.y;
            acc[3][2] += kf.w * vf.z; acc[3][3] += kf.w * vf.w;
        }
        if (tid < 64) {
#pragma unroll 8
            for (int l = 0; l < 64; l++) ksum_acc += ks[l][tid];
        }
        __syncthreads();
    }

    float* kvdst = g_kv + (size_t)(b * 8 + h) * 4096;
#pragma unroll
    for (int i = 0; i < 4; i++)
#pragma unroll
        for (int j = 0; j < 4; j++)
            atomicAdd(&kvdst[(tx * 4 + i) * 64 + (ty * 4 + j)], acc[i][j]);
    if (tid < 64) atomicAdd(&g_ksum[(b * 8 + h) * 64 + tid], ksum_acc);
}

// ---------------- out = (q/z) @ kv -> g_attn[b][f][l] ----------------------------
__global__ __launch_bounds__(256) void attn_out_kernel() {
    int lc = blockIdx.x;            // 0..127, 64 l each
    int h = blockIdx.y, b = blockIdx.z;
    int l0 = lc * 64;
    const float* qb = g_qkv + ((size_t)b * MQKV + h * 64) * SS;

    __shared__ float qs[64][68];    // [d][l]
    __shared__ float kvt[64][64];   // [dk][dv]
    __shared__ float ksum_s[64];
    __shared__ float zs[64];

    int tid = threadIdx.x;
    int tx = tid & 15, ty = tid >> 4;

    const float* kvsrc = g_kv + (size_t)(b * 8 + h) * 4096;
    float* kvflat = &kvt[0][0];
#pragma unroll
    for (int u = 0; u < 4; u++) {
        int idx = u * 1024 + tid * 4;
        *(float4*)(kvflat + idx) = *(const float4*)(kvsrc + idx);
    }
    if (tid < 16)
        *(float4*)&ksum_s[tid * 4] =
            *(const float4*)(g_ksum + (b * 8 + h) * 64 + tid * 4);

    int ld_d = tid >> 2, ld_q = tid & 3;
    const float* qrow = qb + (size_t)ld_d * SS + l0 + ld_q * 16;
#pragma unroll
    for (int u = 0; u < 4; u++) {
        float4 qg = *(const float4*)(qrow + u * 4);
        float4 qe = {elu1(qg.x), elu1(qg.y), elu1(qg.z), elu1(qg.w)};
        *(float4*)&qs[ld_d][ld_q * 16 + u * 4] = qe;
    }
    __syncthreads();

    if (tid < 64) {
        float z = 0.f;
#pragma unroll 8
        for (int d = 0; d < 64; d++) z += qs[d][tid] * ksum_s[d];
        zs[tid] = z;
    }
    __syncthreads();

    float acc[4][4] = {};  // [dv][l]
#pragma unroll 8
    for (int dk = 0; dk < 64; dk++) {
        float4 qf = *(const float4*)&qs[dk][tx * 4];
        float4 kf = *(const float4*)&kvt[dk][ty * 4];
        acc[0][0] += kf.x * qf.x; acc[0][1] += kf.x * qf.y;
        acc[0][2] += kf.x * qf.z; acc[0][3] += kf.x * qf.w;
        acc[1][0] += kf.y * qf.x; acc[1][1] += kf.y * qf.y;
        acc[1][2] += kf.y * qf.z; acc[1][3] += kf.y * qf.w;
        acc[2][0] += kf.z * qf.x; acc[2][1] += kf.z * qf.y;
        acc[2][2] += kf.z * qf.z; acc[2][3] += kf.z * qf.w;
        acc[3][0] += kf.w * qf.x; acc[3][1] += kf.w * qf.y;
        acc[3][2] += kf.w * qf.z; acc[3][3] += kf.w * qf.w;
    }
    float rz0 = 1.f / zs[tx * 4 + 0];
    float rz1 = 1.f / zs[tx * 4 + 1];
    float rz2 = 1.f / zs[tx * 4 + 2];
    float rz3 = 1.f / zs[tx * 4 + 3];

    float* od = g_attn + ((size_t)b * FF + h * 64) * SS + l0;
#pragma unroll
    for (int j = 0; j < 4; j++) {
        float4 o = {acc[j][0] * rz0, acc[j][1] * rz1,
                    acc[j][2] * rz2, acc[j][3] * rz3};
        *(float4*)(od + (size_t)(ty * 4 + j) * SS + tx * 4) = o;
    }
}

// ---------------- final: out = hidden + gate * GN2(y) ---------------------------
__global__ void final_kernel(const float* __restrict__ hs,
                             const float* __restrict__ gate,
                             float* __restrict__ out) {
    size_t i = (size_t)blockIdx.x * 256 + threadIdx.x;  // float4 index
    size_t base = i * 4;
    int row = (int)(base >> 13);  // / 8192
    int f = row & 511;
    int b = row >> 9;
    float sc = g_scale2[b * FF + f];
    float sh = g_shift2[b * FF + f];
    float gt = gate[f];
    float4 hv = *(const float4*)(hs + base);
    float4 yv = *(const float4*)(g_y + base);
    float4 o;
    o.x = hv.x + gt * fmaf(yv.x, sc, sh);
    o.y = hv.y + gt * fmaf(yv.y, sc, sh);
    o.z = hv.z + gt * fmaf(yv.z, sc, sh);
    o.w = hv.w + gt * fmaf(yv.w, sc, sh);
    *(float4*)(out + base) = o;
}

// ---------------- launch ----------------
extern "C" void kernel_launch(void* const* d_in, const int* in_sizes, int n_in,
                              void* d_out, int out_size) {
    const float* hs   = (const float*)d_in[0];  // [B,F,S]
    const float* qkvw = (const float*)d_in[1];  // [3,H,D,F] == [1536][512]
    const float* qkvb = (const float*)d_in[2];  // [1536]
    const float* proj = (const float*)d_in[3];  // [F,F]
    const float* g1g  = (const float*)d_in[4];
    const float* g1b  = (const float*)d_in[5];
    const float* g2g  = (const float*)d_in[6];
    const float* g2b  = (const float*)d_in[7];
    const float* gate = (const float*)d_in[8];  // [F]
    float* out = (float*)d_out;

    gn_stats_kernel<0><<<256, 256>>>(hs, g1g, g1b);
    sgemm_kernel<true><<<dim3(64, 12, 8), 256>>>(qkvw, hs, qkvb);
    zero_kv_kernel<<<1024, 256>>>();
    kv_kernel<<<dim3(32, 8, 8), 256>>>();
    attn_out_kernel<<<dim3(128, 8, 8), 256>>>();
    sgemm_kernel<false><<<dim3(64, 4, 8), 256>>>(proj, nullptr, nullptr);
    gn_stats_kernel<1><<<256, 256>>>(nullptr, g2g, g2b);
    final_kernel<<<32768, 256>>>(hs, gate, out);
}